// round 9
// baseline (speedup 1.0000x reference)
#include <cuda_runtime.h>
#include <cuda_fp16.h>
#include <stdint.h>
#include <math.h>

#define NT   128
#define TILE 128

// packed, XOR-swizzled weight tiles: n-major, row stride = K*2 bytes
#define RS64  128
#define RS128 256

#define NW1H 0
#define NW1L 8192
#define NW2H 16384
#define NW2L 24576
#define AW1H 32768
#define AW1L 49152
#define AW2H 65536
#define AW2L 73728
#define OW1H 81920
#define OW1L 98304
#define OW2H 114688
#define OW2L 122880
#define WBYTES 131072

#define BIAS_OFF WBYTES            // 1536 B (6 x 64 floats)
#define TV_OFF   (BIAS_OFF + 1536)
#define ACT_OFF  (TV_OFF + 256)    // 132864
#define ABUF     (TILE*128)        // 16384 per lo-buffer (swizzled 128B rows)
#define SMEM_REQ (ACT_OFF + 3*ABUF)   // 182016

__device__ __align__(16) unsigned char g_wblob[WBYTES];

// ---------------- helpers ----------------
__device__ __forceinline__ uint32_t smem_u32(const void* p) {
    uint32_t a;
    asm("{ .reg .u64 t; cvta.to.shared.u64 t, %1; cvt.u32.u64 %0, t; }" : "=r"(a) : "l"(p));
    return a;
}

__device__ __forceinline__ void split2(float x0, float x1, uint32_t& hi, uint32_t& lo) {
    __half h0 = __float2half_rn(x0), h1 = __float2half_rn(x1);
    __half l0 = __float2half_rn(x0 - __half2float(h0));
    __half l1 = __float2half_rn(x1 - __half2float(h1));
    __half2 H = __halves2half2(h0, h1), L = __halves2half2(l0, l1);
    hi = *reinterpret_cast<uint32_t*>(&H);
    lo = *reinterpret_cast<uint32_t*>(&L);
}

#define MMA(D, a0, a1, a2, a3, b0, b1) \
    asm volatile("mma.sync.aligned.m16n8k16.row.col.f32.f16.f16.f32 " \
        "{%0,%1,%2,%3},{%4,%5,%6,%7},{%8,%9},{%0,%1,%2,%3};" \
        : "+f"((D)[0]), "+f"((D)[1]), "+f"((D)[2]), "+f"((D)[3]) \
        : "r"(a0), "r"(a1), "r"(a2), "r"(a3), "r"(b0), "r"(b1))

#define LDSM4(r0, r1, r2, r3, a) \
    asm volatile("ldmatrix.sync.aligned.m8n8.x4.shared.b16 {%0,%1,%2,%3}, [%4];" \
        : "=r"(r0), "=r"(r1), "=r"(r2), "=r"(r3) : "r"(a))

#define STS32(a, v) asm volatile("st.shared.b32 [%0], %1;" :: "r"(a), "r"(v) : "memory")

struct Slot { uint32_t h[32]; };   // activation hi halves, 2 row-blocks (lo in smem)

// ---------------- weight conversion: fp32 -> fp16 hi/lo, packed swizzled ----------------
__global__ void convert_weights(const float* __restrict__ nW1, const float* __restrict__ nW2,
                                const float* __restrict__ aW1, const float* __restrict__ aW2,
                                const float* __restrict__ oW1, const float* __restrict__ oW2) {
    int i = blockIdx.x * blockDim.x + threadIdx.x;
    if (i >= 32768) return;
    int idx = i; const float* src; int hb, lb, rs;
    if (idx < 4096)       { src = nW1; hb = NW1H; lb = NW1L; rs = RS64; }
    else if (idx < 8192)  { idx -= 4096;  src = nW2; hb = NW2H; lb = NW2L; rs = RS64; }
    else if (idx < 16384) { idx -= 8192;  src = aW1; hb = AW1H; lb = AW1L; rs = RS128; }
    else if (idx < 20480) { idx -= 16384; src = aW2; hb = AW2H; lb = AW2L; rs = RS64; }
    else if (idx < 28672) { idx -= 20480; src = oW1; hb = OW1H; lb = OW1L; rs = RS128; }
    else                  { idx -= 28672; src = oW2; hb = OW2H; lb = OW2L; rs = RS64; }
    int k = idx >> 6, n = idx & 63;          // source row-major [K][64]
    float w = src[idx];
    __half h = __float2half_rn(w);
    __half l = __float2half_rn(w - __half2float(h));
    int off = n * rs + (((k >> 3) ^ (n & 7)) << 4) + (k & 7) * 2;
    *(__half*)(g_wblob + hb + off) = h;
    *(__half*)(g_wblob + lb + off) = l;
}

// ---------------- core compute ----------------
__device__ __forceinline__ void zeroD(float (&D)[16][4]) {
#pragma unroll
    for (int n = 0; n < 16; n++)
#pragma unroll
        for (int i = 0; i < 4; i++) D[n][i] = 0.f;
}

// one K=64 chunk over 32 rows: D += Ah*Wh + Al*Wh + Ah*Wl
__device__ __forceinline__ void chunk64(float (&D)[16][4], const Slot& A, uint32_t aRd,
                                        uint32_t baseH, uint32_t baseL, int rs, int kc0,
                                        int bn, int hk8, int hk16, int rn7) {
#pragma unroll
    for (int kt = 0; kt < 4; kt++) {
        uint32_t xw = (uint32_t)(((kc0 + kt*2 + hk8) ^ rn7) << 4);
        uint32_t xa = (uint32_t)(((kt*2 + hk16) ^ rn7) << 4);
        uint32_t al[2][4];
        LDSM4(al[0][0], al[0][1], al[0][2], al[0][3], aRd + xa);
        LDSM4(al[1][0], al[1][1], al[1][2], al[1][3], aRd + 2048u + xa);
        uint32_t h[4][4];
#pragma unroll
        for (int np = 0; np < 4; np++) {
            uint32_t ro = (uint32_t)((np*16 + bn) * rs) + xw;
            LDSM4(h[np][0], h[np][1], h[np][2], h[np][3], baseH + ro);
        }
#pragma unroll
        for (int nb = 0; nb < 2; nb++) {
            const uint32_t a0 = A.h[nb*16 + kt*4],     a1 = A.h[nb*16 + kt*4 + 1];
            const uint32_t a2 = A.h[nb*16 + kt*4 + 2], a3 = A.h[nb*16 + kt*4 + 3];
#pragma unroll
            for (int np = 0; np < 4; np++) {
                MMA(D[nb*8 + 2*np],   a0, a1, a2, a3, h[np][0], h[np][1]);
                MMA(D[nb*8 + 2*np+1], a0, a1, a2, a3, h[np][2], h[np][3]);
            }
        }
#pragma unroll
        for (int nb = 0; nb < 2; nb++) {
#pragma unroll
            for (int np = 0; np < 4; np++) {
                MMA(D[nb*8 + 2*np],   al[nb][0], al[nb][1], al[nb][2], al[nb][3], h[np][0], h[np][1]);
                MMA(D[nb*8 + 2*np+1], al[nb][0], al[nb][1], al[nb][2], al[nb][3], h[np][2], h[np][3]);
            }
        }
        uint32_t l[4][4];
#pragma unroll
        for (int np = 0; np < 4; np++) {
            uint32_t ro = (uint32_t)((np*16 + bn) * rs) + xw;
            LDSM4(l[np][0], l[np][1], l[np][2], l[np][3], baseL + ro);
        }
#pragma unroll
        for (int nb = 0; nb < 2; nb++) {
            const uint32_t a0 = A.h[nb*16 + kt*4],     a1 = A.h[nb*16 + kt*4 + 1];
            const uint32_t a2 = A.h[nb*16 + kt*4 + 2], a3 = A.h[nb*16 + kt*4 + 3];
#pragma unroll
            for (int np = 0; np < 4; np++) {
                MMA(D[nb*8 + 2*np],   a0, a1, a2, a3, l[np][0], l[np][1]);
                MMA(D[nb*8 + 2*np+1], a0, a1, a2, a3, l[np][2], l[np][3]);
            }
        }
    }
}

// D + bias (+lrelu) -> hi into regs (A-frag layout), lo into swizzled smem buffer
__device__ __forceinline__ void epi_slot(float (&D)[16][4], const float* __restrict__ bias,
                                         bool lrelu, Slot& S, uint32_t wAddr, int g7, int lane) {
    int c0 = 2 * (lane & 3);
#pragma unroll
    for (int nb = 0; nb < 2; nb++) {
#pragma unroll
        for (int nt = 0; nt < 8; nt++) {
            float b0 = bias[nt*8 + c0], b1 = bias[nt*8 + c0 + 1];
            float x0 = D[nb*8 + nt][0] + b0, x1 = D[nb*8 + nt][1] + b1;
            float x2 = D[nb*8 + nt][2] + b0, x3 = D[nb*8 + nt][3] + b1;
            if (lrelu) {
                x0 = x0 > 0.f ? x0 : 0.01f * x0;
                x1 = x1 > 0.f ? x1 : 0.01f * x1;
                x2 = x2 > 0.f ? x2 : 0.01f * x2;
                x3 = x3 > 0.f ? x3 : 0.01f * x3;
            }
            int r = nb*16 + (nt >> 1) * 4 + (nt & 1) * 2;
            uint32_t lo01, lo23;
            split2(x0, x1, S.h[r],     lo01);
            split2(x2, x3, S.h[r + 1], lo23);
            uint32_t a = wAddr + (uint32_t)(nb*2048) + (uint32_t)((nt ^ g7) << 4);
            STS32(a,        lo01);   // row g
            STS32(a + 1024, lo23);   // row g+8
        }
    }
    __syncwarp();
}

// two-layer MLP: H shares S2's registers (caller guarantees S2's value is dead);
// H-lo shares the DST slot's smem buffer. Leaves raw layer-2 accumulators in D.
__device__ __forceinline__ void mlp(float (&D)[16][4], Slot& H,
                                    const Slot& in1, const Slot* in2,
                                    uint32_t a1Rd, uint32_t a2Rd,
                                    uint32_t hRd, uint32_t hWr, uint32_t sb,
                                    uint32_t w1h, uint32_t w1l, int rs1, const float* b1,
                                    uint32_t w2h, uint32_t w2l,
                                    int bn, int hk8, int hk16, int rn7, int g7, int lane) {
    zeroD(D);
    chunk64(D, in1, a1Rd, sb + w1h, sb + w1l, rs1, 0, bn, hk8, hk16, rn7);
    if (in2) chunk64(D, *in2, a2Rd, sb + w1h, sb + w1l, rs1, 8, bn, hk8, hk16, rn7);
    epi_slot(D, b1, true, H, hWr, g7, lane);
    zeroD(D);
    chunk64(D, H, hRd, sb + w2h, sb + w2l, RS64, 0, bn, hk8, hk16, rn7);
}

// gather 4 embedding rows (r1, +8, +16, +24): hi into regs, lo into swizzled smem
__device__ __forceinline__ void gather(Slot& S, uint32_t wAddr, int g7,
                                       const float* __restrict__ item,
                                       int i0, int i1, int i2, int i3, int lane) {
    const float* p[4] = {
        item + (size_t)i0 * 64 + 2 * (lane & 3),
        item + (size_t)i1 * 64 + 2 * (lane & 3),
        item + (size_t)i2 * 64 + 2 * (lane & 3),
        item + (size_t)i3 * 64 + 2 * (lane & 3) };
#pragma unroll
    for (int nb = 0; nb < 2; nb++) {
        const float* pa = p[nb*2];
        const float* pb = p[nb*2 + 1];
#pragma unroll
        for (int j = 0; j < 4; j++) {
            float2 a = *(const float2*)(pa + j * 16);
            float2 b = *(const float2*)(pb + j * 16);
            float2 c = *(const float2*)(pa + j * 16 + 8);
            float2 d = *(const float2*)(pb + j * 16 + 8);
            uint32_t lo;
            uint32_t a0 = wAddr + (uint32_t)(nb*2048) + (uint32_t)(((2*j)     ^ g7) << 4);
            uint32_t a1 = wAddr + (uint32_t)(nb*2048) + (uint32_t)(((2*j + 1) ^ g7) << 4);
            split2(a.x, a.y, S.h[nb*16 + j*4+0], lo); STS32(a0,        lo);
            split2(b.x, b.y, S.h[nb*16 + j*4+1], lo); STS32(a0 + 1024, lo);
            split2(c.x, c.y, S.h[nb*16 + j*4+2], lo); STS32(a1,        lo);
            split2(d.x, d.y, S.h[nb*16 + j*4+3], lo); STS32(a1 + 1024, lo);
        }
    }
    __syncwarp();
}

// cosine-similarity epilogue on raw layer-2 accumulators (4 rows per lane-quad)
__device__ __forceinline__ void final_epi(float (&D)[16][4], const float* __restrict__ bias,
                                          const float* __restrict__ tv, float tnorm,
                                          float* __restrict__ outp, int r1, int lane) {
    int c0 = 2 * (lane & 3);
#pragma unroll
    for (int nb = 0; nb < 2; nb++) {
        float n1 = 0.f, s1 = 0.f, n2 = 0.f, s2 = 0.f;
#pragma unroll
        for (int nt = 0; nt < 8; nt++) {
            float b0 = bias[nt*8 + c0], b1 = bias[nt*8 + c0 + 1];
            float t0 = tv[nt*8 + c0],  t1 = tv[nt*8 + c0 + 1];
            float x0 = D[nb*8 + nt][0] + b0, x1 = D[nb*8 + nt][1] + b1;
            float x2 = D[nb*8 + nt][2] + b0, x3 = D[nb*8 + nt][3] + b1;
            n1 = fmaf(x0, t0, fmaf(x1, t1, n1));  s1 = fmaf(x0, x0, fmaf(x1, x1, s1));
            n2 = fmaf(x2, t0, fmaf(x3, t1, n2));  s2 = fmaf(x2, x2, fmaf(x3, x3, s2));
        }
        n1 += __shfl_xor_sync(~0u, n1, 1); n1 += __shfl_xor_sync(~0u, n1, 2);
        s1 += __shfl_xor_sync(~0u, s1, 1); s1 += __shfl_xor_sync(~0u, s1, 2);
        n2 += __shfl_xor_sync(~0u, n2, 1); n2 += __shfl_xor_sync(~0u, n2, 2);
        s2 += __shfl_xor_sync(~0u, s2, 1); s2 += __shfl_xor_sync(~0u, s2, 2);
        if ((lane & 3) == 0) {
            float dn = fmaxf(tnorm, 1e-8f);
            outp[r1 + nb*16]     = n1 / (fmaxf(sqrtf(s1), 1e-8f) * dn) * 10.0f;
            outp[r1 + nb*16 + 8] = n2 / (fmaxf(sqrtf(s2), 1e-8f) * dn) * 10.0f;
        }
    }
}

// ---------------- main kernel ----------------
__global__ void __launch_bounds__(NT, 1) logicnet_mma(
    const int* __restrict__ seq, const int* __restrict__ post, const int* __restrict__ negt,
    const float* __restrict__ item, const float* __restrict__ tvec,
    const float* __restrict__ nb1, const float* __restrict__ nb2,
    const float* __restrict__ ab1, const float* __restrict__ ab2,
    const float* __restrict__ ob1, const float* __restrict__ ob2,
    float* __restrict__ out, int batch)
{
    extern __shared__ unsigned char sm[];
    {   // stage pre-split, pre-swizzled weights
        const float4* s4 = (const float4*)g_wblob;
        float4* d4 = (float4*)sm;
#pragma unroll 4
        for (int i = threadIdx.x; i < WBYTES / 16; i += NT) d4[i] = s4[i];
    }
    float* bias = (float*)(sm + BIAS_OFF);
    if (threadIdx.x < 64) {
        int t = threadIdx.x;
        bias[t]       = nb1[t]; bias[64 + t]  = nb2[t];
        bias[128 + t] = ab1[t]; bias[192 + t] = ab2[t];
        bias[256 + t] = ob1[t]; bias[320 + t] = ob2[t];
        ((float*)(sm + TV_OFF))[t] = tvec[t];
    }
    __syncthreads();

    const int lane = threadIdx.x & 31;
    const int wid  = threadIdx.x >> 5;
    const int wrow = wid * 32;

    const uint32_t sb = smem_u32(sm);
    const float* tv = (const float*)(sm + TV_OFF);
    const int bn   = (lane & 7) + ((lane >> 4) << 3);
    const int hk8  = (lane >> 3) & 1;
    const int hk16 = lane >> 4;
    const int rn7  = lane & 7;
    const int g7   = (lane >> 2) & 7;
    const int r1 = blockIdx.x * TILE + wrow + (lane >> 2);

    // act-lo smem addressing (swizzled 128B rows, warp-private 32-row region)
    const uint32_t rdB = sb + ACT_OFF + (uint32_t)((wrow + (lane & 15)) * 128);
    const uint32_t wrB = sb + ACT_OFF + (uint32_t)((wrow + (lane >> 2)) * 128 + ((lane & 3) << 2));
    const uint32_t rdP0 = rdB,  rdP1 = rdB + ABUF,  rdP2 = rdB + 2*ABUF;
    const uint32_t wrP0 = wrB,  wrP1 = wrB + ABUF,  wrP2 = wrB + 2*ABUF;

    float tn = tv[lane] * tv[lane] + tv[lane + 32] * tv[lane + 32];
#pragma unroll
    for (int m = 16; m; m >>= 1) tn += __shfl_xor_sync(~0u, tn, m);
    const float tnorm = sqrtf(tn);

    Slot S0, S1, S2;            // H aliases S2's registers (liveness-safe)
    float D[16][4];

    const int q0 = r1, q1 = r1 + 8, q2 = r1 + 16, q3 = r1 + 24;

    gather(S0, wrP0, g7, item, seq[q0*5+0], seq[q1*5+0], seq[q2*5+0], seq[q3*5+0], lane); // e0
    gather(S1, wrP1, g7, item, seq[q0*5+1], seq[q1*5+1], seq[q2*5+1], seq[q3*5+1], lane); // e1
    // n1 = NOT(e1) -> S1/P1   (H=S2 regs, H-lo in P1)
    mlp(D, S2, S1, nullptr, rdP1, 0,    rdP1, wrP1, sb, NW1H, NW1L, RS64,  bias+0,   NW2H, NW2L, bn, hk8, hk16, rn7, g7, lane);
    epi_slot(D, bias + 64, false, S1, wrP1, g7, lane);
    // i5 = AND(e0, n1) -> S0/P0
    mlp(D, S2, S0, &S1,     rdP0, rdP1, rdP0, wrP0, sb, AW1H, AW1L, RS128, bias+128, AW2H, AW2L, bn, hk8, hk16, rn7, g7, lane);
    epi_slot(D, bias + 192, false, S0, wrP0, g7, lane);
    gather(S1, wrP1, g7, item, seq[q0*5+2], seq[q1*5+2], seq[q2*5+2], seq[q3*5+2], lane); // e2
    gather(S2, wrP2, g7, item, seq[q0*5+3], seq[q1*5+3], seq[q2*5+3], seq[q3*5+3], lane); // e3
    // i6 = OR(e2, e3) -> S1/P1   (e3 consumed in layer1 before H overwrites S2)
    mlp(D, S2, S1, &S2,     rdP1, rdP2, rdP1, wrP1, sb, OW1H, OW1L, RS128, bias+256, OW2H, OW2L, bn, hk8, hk16, rn7, g7, lane);
    epi_slot(D, bias + 320, false, S1, wrP1, g7, lane);
    // i7 = AND(i5, i6) -> S0/P0
    mlp(D, S2, S0, &S1,     rdP0, rdP1, rdP0, wrP0, sb, AW1H, AW1L, RS128, bias+128, AW2H, AW2L, bn, hk8, hk16, rn7, g7, lane);
    epi_slot(D, bias + 192, false, S0, wrP0, g7, lane);
    // n7 = NOT(i7) -> S1/P1
    mlp(D, S2, S0, nullptr, rdP0, 0,    rdP1, wrP1, sb, NW1H, NW1L, RS64,  bias+0,   NW2H, NW2L, bn, hk8, hk16, rn7, g7, lane);
    epi_slot(D, bias + 64, false, S1, wrP1, g7, lane);
    gather(S2, wrP2, g7, item, seq[q0*5+4], seq[q1*5+4], seq[q2*5+4], seq[q3*5+4], lane); // e4
    // i8 = OR(n7, e4) -> S0/P0
    mlp(D, S2, S1, &S2,     rdP1, rdP2, rdP0, wrP0, sb, OW1H, OW1L, RS128, bias+256, OW2H, OW2L, bn, hk8, hk16, rn7, g7, lane);
    epi_slot(D, bias + 320, false, S0, wrP0, g7, lane);
    // enc_not = NOT(i8) -> S1/P1
    mlp(D, S2, S0, nullptr, rdP0, 0,    rdP1, wrP1, sb, NW1H, NW1L, RS64,  bias+0,   NW2H, NW2L, bn, hk8, hk16, rn7, g7, lane);
    epi_slot(D, bias + 64, false, S1, wrP1, g7, lane);
    gather(S2, wrP2, g7, item, post[q0], post[q1], post[q2], post[q3], lane);             // pos_e
    // encoded_pos = OR(enc_not, pos_e)   (H uses free buffer P0)
    mlp(D, S2, S1, &S2,     rdP1, rdP2, rdP0, wrP0, sb, OW1H, OW1L, RS128, bias+256, OW2H, OW2L, bn, hk8, hk16, rn7, g7, lane);
    final_epi(D, bias + 320, tv, tnorm, out, r1, lane);
    gather(S2, wrP2, g7, item, negt[q0], negt[q1], negt[q2], negt[q3], lane);             // neg_e
    // encoded_neg = OR(enc_not, neg_e)
    mlp(D, S2, S1, &S2,     rdP1, rdP2, rdP0, wrP0, sb, OW1H, OW1L, RS128, bias+256, OW2H, OW2L, bn, hk8, hk16, rn7, g7, lane);
    final_epi(D, bias + 320, tv, tnorm, out + batch, r1, lane);
}

extern "C" void kernel_launch(void* const* d_in, const int* in_sizes, int n_in,
                              void* d_out, int out_size) {
    const int*   seq   = (const int*)  d_in[0];
    const int*   pos_t = (const int*)  d_in[1];
    const int*   neg_t = (const int*)  d_in[2];
    const float* item  = (const float*)d_in[3];
    const float* tvec  = (const float*)d_in[4];
    const float* nW1 = (const float*)d_in[5];
    const float* nb1 = (const float*)d_in[6];
    const float* nW2 = (const float*)d_in[7];
    const float* nb2 = (const float*)d_in[8];
    const float* aW1 = (const float*)d_in[9];
    const float* ab1 = (const float*)d_in[10];
    const float* aW2 = (const float*)d_in[11];
    const float* ab2 = (const float*)d_in[12];
    const float* oW1 = (const float*)d_in[13];
    const float* ob1 = (const float*)d_in[14];
    const float* oW2 = (const float*)d_in[15];
    const float* ob2 = (const float*)d_in[16];
    float* out = (float*)d_out;

    int batch = in_sizes[1];
    convert_weights<<<128, 256>>>(nW1, nW2, aW1, aW2, oW1, oW2);

    int grid = batch / TILE;
    cudaFuncSetAttribute(logicnet_mma, cudaFuncAttributeMaxDynamicSharedMemorySize, SMEM_REQ);
    logicnet_mma<<<grid, NT, SMEM_REQ>>>(
        seq, pos_t, neg_t, item, tvec,
        nb1, nb2, ab1, ab2, ob1, ob2, out, batch);
}

// round 11
// speedup vs baseline: 1.1435x; 1.1435x over previous
#include <cuda_runtime.h>
#include <cuda_fp16.h>
#include <stdint.h>
#include <math.h>

#define NT   256
#define TILE 256

// packed, XOR-swizzled weight tiles: n-major, row stride = K*2 bytes
#define RS64  128
#define RS128 256

#define NW1H 0
#define NW1L 8192
#define NW2H 16384
#define NW2L 24576
#define AW1H 32768
#define AW1L 49152
#define AW2H 65536
#define AW2L 73728
#define OW1H 81920
#define OW1L 98304
#define OW2H 114688
#define OW2L 122880
#define WBYTES 131072

#define BIAS_OFF WBYTES            // 1536 B (6 x 64 floats)
#define TV_OFF   (BIAS_OFF + 1536)
#define ACT_OFF  (TV_OFF + 256)    // 132864
#define ABUF     (TILE*128)        // 32768 per lo-buffer (swizzled 128B rows)
#define SMEM_REQ (ACT_OFF + 3*ABUF)   // 231168  (<= 232448 sm_103 cap)

__device__ __align__(16) unsigned char g_wblob[WBYTES];

// ---------------- helpers ----------------
__device__ __forceinline__ uint32_t smem_u32(const void* p) {
    uint32_t a;
    asm("{ .reg .u64 t; cvta.to.shared.u64 t, %1; cvt.u32.u64 %0, t; }" : "=r"(a) : "l"(p));
    return a;
}

__device__ __forceinline__ void split2(float x0, float x1, uint32_t& hi, uint32_t& lo) {
    __half h0 = __float2half_rn(x0), h1 = __float2half_rn(x1);
    __half l0 = __float2half_rn(x0 - __half2float(h0));
    __half l1 = __float2half_rn(x1 - __half2float(h1));
    __half2 H = __halves2half2(h0, h1), L = __halves2half2(l0, l1);
    hi = *reinterpret_cast<uint32_t*>(&H);
    lo = *reinterpret_cast<uint32_t*>(&L);
}

#define MMA(D, a0, a1, a2, a3, b0, b1) \
    asm volatile("mma.sync.aligned.m16n8k16.row.col.f32.f16.f16.f32 " \
        "{%0,%1,%2,%3},{%4,%5,%6,%7},{%8,%9},{%0,%1,%2,%3};" \
        : "+f"((D)[0]), "+f"((D)[1]), "+f"((D)[2]), "+f"((D)[3]) \
        : "r"(a0), "r"(a1), "r"(a2), "r"(a3), "r"(b0), "r"(b1))

#define LDSM4(r0, r1, r2, r3, a) \
    asm volatile("ldmatrix.sync.aligned.m8n8.x4.shared.b16 {%0,%1,%2,%3}, [%4];" \
        : "=r"(r0), "=r"(r1), "=r"(r2), "=r"(r3) : "r"(a))

#define STS32(a, v) asm volatile("st.shared.b32 [%0], %1;" :: "r"(a), "r"(v) : "memory")

struct Slot { uint32_t h[32]; };   // activation hi halves, 2 row-blocks (lo in smem)

// ---------------- weight conversion: fp32 -> fp16 hi/lo, packed swizzled ----------------
__global__ void convert_weights(const float* __restrict__ nW1, const float* __restrict__ nW2,
                                const float* __restrict__ aW1, const float* __restrict__ aW2,
                                const float* __restrict__ oW1, const float* __restrict__ oW2) {
    int i = blockIdx.x * blockDim.x + threadIdx.x;
    if (i >= 32768) return;
    int idx = i; const float* src; int hb, lb, rs;
    if (idx < 4096)       { src = nW1; hb = NW1H; lb = NW1L; rs = RS64; }
    else if (idx < 8192)  { idx -= 4096;  src = nW2; hb = NW2H; lb = NW2L; rs = RS64; }
    else if (idx < 16384) { idx -= 8192;  src = aW1; hb = AW1H; lb = AW1L; rs = RS128; }
    else if (idx < 20480) { idx -= 16384; src = aW2; hb = AW2H; lb = AW2L; rs = RS64; }
    else if (idx < 28672) { idx -= 20480; src = oW1; hb = OW1H; lb = OW1L; rs = RS128; }
    else                  { idx -= 28672; src = oW2; hb = OW2H; lb = OW2L; rs = RS64; }
    int k = idx >> 6, n = idx & 63;          // source row-major [K][64]
    float w = src[idx];
    __half h = __float2half_rn(w);
    __half l = __float2half_rn(w - __half2float(h));
    int off = n * rs + (((k >> 3) ^ (n & 7)) << 4) + (k & 7) * 2;
    *(__half*)(g_wblob + hb + off) = h;
    *(__half*)(g_wblob + lb + off) = l;
}

// ---------------- core compute ----------------
__device__ __forceinline__ void zeroD(float (&D)[16][4]) {
#pragma unroll
    for (int n = 0; n < 16; n++)
#pragma unroll
        for (int i = 0; i < 4; i++) D[n][i] = 0.f;
}

// one K=64 chunk over 32 rows: D += Ah*Wh + Al*Wh + Ah*Wl
// NOTE: second row-block of the warp-private act-lo region is +16 rows = +2048 B
__device__ __forceinline__ void chunk64(float (&D)[16][4], const Slot& A, uint32_t aRd,
                                        uint32_t baseH, uint32_t baseL, int rs, int kc0,
                                        int bn, int hk8, int hk16, int rn7) {
#pragma unroll
    for (int kt = 0; kt < 4; kt++) {
        uint32_t xw = (uint32_t)(((kc0 + kt*2 + hk8) ^ rn7) << 4);
        uint32_t xa = (uint32_t)(((kt*2 + hk16) ^ rn7) << 4);
        uint32_t al[2][4];
        LDSM4(al[0][0], al[0][1], al[0][2], al[0][3], aRd + xa);
        LDSM4(al[1][0], al[1][1], al[1][2], al[1][3], aRd + 2048u + xa);
        uint32_t h[4][4];
#pragma unroll
        for (int np = 0; np < 4; np++) {
            uint32_t ro = (uint32_t)((np*16 + bn) * rs) + xw;
            LDSM4(h[np][0], h[np][1], h[np][2], h[np][3], baseH + ro);
        }
#pragma unroll
        for (int nb = 0; nb < 2; nb++) {
            const uint32_t a0 = A.h[nb*16 + kt*4],     a1 = A.h[nb*16 + kt*4 + 1];
            const uint32_t a2 = A.h[nb*16 + kt*4 + 2], a3 = A.h[nb*16 + kt*4 + 3];
#pragma unroll
            for (int np = 0; np < 4; np++) {
                MMA(D[nb*8 + 2*np],   a0, a1, a2, a3, h[np][0], h[np][1]);
                MMA(D[nb*8 + 2*np+1], a0, a1, a2, a3, h[np][2], h[np][3]);
            }
        }
#pragma unroll
        for (int nb = 0; nb < 2; nb++) {
#pragma unroll
            for (int np = 0; np < 4; np++) {
                MMA(D[nb*8 + 2*np],   al[nb][0], al[nb][1], al[nb][2], al[nb][3], h[np][0], h[np][1]);
                MMA(D[nb*8 + 2*np+1], al[nb][0], al[nb][1], al[nb][2], al[nb][3], h[np][2], h[np][3]);
            }
        }
        uint32_t l[4][4];
#pragma unroll
        for (int np = 0; np < 4; np++) {
            uint32_t ro = (uint32_t)((np*16 + bn) * rs) + xw;
            LDSM4(l[np][0], l[np][1], l[np][2], l[np][3], baseL + ro);
        }
#pragma unroll
        for (int nb = 0; nb < 2; nb++) {
            const uint32_t a0 = A.h[nb*16 + kt*4],     a1 = A.h[nb*16 + kt*4 + 1];
            const uint32_t a2 = A.h[nb*16 + kt*4 + 2], a3 = A.h[nb*16 + kt*4 + 3];
#pragma unroll
            for (int np = 0; np < 4; np++) {
                MMA(D[nb*8 + 2*np],   a0, a1, a2, a3, l[np][0], l[np][1]);
                MMA(D[nb*8 + 2*np+1], a0, a1, a2, a3, l[np][2], l[np][3]);
            }
        }
    }
}

// D + bias (+lrelu) -> hi into regs (A-frag layout), lo into swizzled smem buffer
__device__ __forceinline__ void epi_slot(float (&D)[16][4], const float* __restrict__ bias,
                                         bool lrelu, Slot& S, uint32_t wAddr, int g7, int lane) {
    int c0 = 2 * (lane & 3);
#pragma unroll
    for (int nb = 0; nb < 2; nb++) {
#pragma unroll
        for (int nt = 0; nt < 8; nt++) {
            float b0 = bias[nt*8 + c0], b1 = bias[nt*8 + c0 + 1];
            float x0 = D[nb*8 + nt][0] + b0, x1 = D[nb*8 + nt][1] + b1;
            float x2 = D[nb*8 + nt][2] + b0, x3 = D[nb*8 + nt][3] + b1;
            if (lrelu) {
                x0 = x0 > 0.f ? x0 : 0.01f * x0;
                x1 = x1 > 0.f ? x1 : 0.01f * x1;
                x2 = x2 > 0.f ? x2 : 0.01f * x2;
                x3 = x3 > 0.f ? x3 : 0.01f * x3;
            }
            int r = nb*16 + (nt >> 1) * 4 + (nt & 1) * 2;
            uint32_t lo01, lo23;
            split2(x0, x1, S.h[r],     lo01);
            split2(x2, x3, S.h[r + 1], lo23);
            uint32_t a = wAddr + (uint32_t)(nb*2048) + (uint32_t)((nt ^ g7) << 4);
            STS32(a,        lo01);   // row g
            STS32(a + 1024, lo23);   // row g+8
        }
    }
    __syncwarp();
}

// two-layer MLP: H shares S2's registers (caller guarantees S2's value is dead);
// H-lo shares the DST slot's smem buffer. Leaves raw layer-2 accumulators in D.
__device__ __forceinline__ void mlp(float (&D)[16][4], Slot& H,
                                    const Slot& in1, const Slot* in2,
                                    uint32_t a1Rd, uint32_t a2Rd,
                                    uint32_t hRd, uint32_t hWr, uint32_t sb,
                                    uint32_t w1h, uint32_t w1l, int rs1, const float* b1,
                                    uint32_t w2h, uint32_t w2l,
                                    int bn, int hk8, int hk16, int rn7, int g7, int lane) {
    zeroD(D);
    chunk64(D, in1, a1Rd, sb + w1h, sb + w1l, rs1, 0, bn, hk8, hk16, rn7);
    if (in2) chunk64(D, *in2, a2Rd, sb + w1h, sb + w1l, rs1, 8, bn, hk8, hk16, rn7);
    epi_slot(D, b1, true, H, hWr, g7, lane);
    zeroD(D);
    chunk64(D, H, hRd, sb + w2h, sb + w2l, RS64, 0, bn, hk8, hk16, rn7);
}

// gather 4 embedding rows (r1, +8, +16, +24): hi into regs, lo into swizzled smem
__device__ __forceinline__ void gather(Slot& S, uint32_t wAddr, int g7,
                                       const float* __restrict__ item,
                                       int i0, int i1, int i2, int i3, int lane) {
    const float* p[4] = {
        item + (size_t)i0 * 64 + 2 * (lane & 3),
        item + (size_t)i1 * 64 + 2 * (lane & 3),
        item + (size_t)i2 * 64 + 2 * (lane & 3),
        item + (size_t)i3 * 64 + 2 * (lane & 3) };
#pragma unroll
    for (int nb = 0; nb < 2; nb++) {
        const float* pa = p[nb*2];
        const float* pb = p[nb*2 + 1];
#pragma unroll
        for (int j = 0; j < 4; j++) {
            float2 a = *(const float2*)(pa + j * 16);
            float2 b = *(const float2*)(pb + j * 16);
            float2 c = *(const float2*)(pa + j * 16 + 8);
            float2 d = *(const float2*)(pb + j * 16 + 8);
            uint32_t lo;
            uint32_t a0 = wAddr + (uint32_t)(nb*2048) + (uint32_t)(((2*j)     ^ g7) << 4);
            uint32_t a1 = wAddr + (uint32_t)(nb*2048) + (uint32_t)(((2*j + 1) ^ g7) << 4);
            split2(a.x, a.y, S.h[nb*16 + j*4+0], lo); STS32(a0,        lo);
            split2(b.x, b.y, S.h[nb*16 + j*4+1], lo); STS32(a0 + 1024, lo);
            split2(c.x, c.y, S.h[nb*16 + j*4+2], lo); STS32(a1,        lo);
            split2(d.x, d.y, S.h[nb*16 + j*4+3], lo); STS32(a1 + 1024, lo);
        }
    }
    __syncwarp();
}

// cosine-similarity epilogue on raw layer-2 accumulators (4 rows per lane-quad)
__device__ __forceinline__ void final_epi(float (&D)[16][4], const float* __restrict__ bias,
                                          const float* __restrict__ tv, float tnorm,
                                          float* __restrict__ outp, int r1, int lane) {
    int c0 = 2 * (lane & 3);
#pragma unroll
    for (int nb = 0; nb < 2; nb++) {
        float n1 = 0.f, s1 = 0.f, n2 = 0.f, s2 = 0.f;
#pragma unroll
        for (int nt = 0; nt < 8; nt++) {
            float b0 = bias[nt*8 + c0], b1 = bias[nt*8 + c0 + 1];
            float t0 = tv[nt*8 + c0],  t1 = tv[nt*8 + c0 + 1];
            float x0 = D[nb*8 + nt][0] + b0, x1 = D[nb*8 + nt][1] + b1;
            float x2 = D[nb*8 + nt][2] + b0, x3 = D[nb*8 + nt][3] + b1;
            n1 = fmaf(x0, t0, fmaf(x1, t1, n1));  s1 = fmaf(x0, x0, fmaf(x1, x1, s1));
            n2 = fmaf(x2, t0, fmaf(x3, t1, n2));  s2 = fmaf(x2, x2, fmaf(x3, x3, s2));
        }
        n1 += __shfl_xor_sync(~0u, n1, 1); n1 += __shfl_xor_sync(~0u, n1, 2);
        s1 += __shfl_xor_sync(~0u, s1, 1); s1 += __shfl_xor_sync(~0u, s1, 2);
        n2 += __shfl_xor_sync(~0u, n2, 1); n2 += __shfl_xor_sync(~0u, n2, 2);
        s2 += __shfl_xor_sync(~0u, s2, 1); s2 += __shfl_xor_sync(~0u, s2, 2);
        if ((lane & 3) == 0) {
            float dn = fmaxf(tnorm, 1e-8f);
            outp[r1 + nb*16]     = n1 / (fmaxf(sqrtf(s1), 1e-8f) * dn) * 10.0f;
            outp[r1 + nb*16 + 8] = n2 / (fmaxf(sqrtf(s2), 1e-8f) * dn) * 10.0f;
        }
    }
}

// ---------------- main kernel ----------------
__global__ void __launch_bounds__(NT, 1) logicnet_mma(
    const int* __restrict__ seq, const int* __restrict__ post, const int* __restrict__ negt,
    const float* __restrict__ item, const float* __restrict__ tvec,
    const float* __restrict__ nb1, const float* __restrict__ nb2,
    const float* __restrict__ ab1, const float* __restrict__ ab2,
    const float* __restrict__ ob1, const float* __restrict__ ob2,
    float* __restrict__ out, int batch)
{
    extern __shared__ unsigned char sm[];
    {   // stage pre-split, pre-swizzled weights
        const float4* s4 = (const float4*)g_wblob;
        float4* d4 = (float4*)sm;
#pragma unroll 4
        for (int i = threadIdx.x; i < WBYTES / 16; i += NT) d4[i] = s4[i];
    }
    float* bias = (float*)(sm + BIAS_OFF);
    if (threadIdx.x < 64) {
        int t = threadIdx.x;
        bias[t]       = nb1[t]; bias[64 + t]  = nb2[t];
        bias[128 + t] = ab1[t]; bias[192 + t] = ab2[t];
        bias[256 + t] = ob1[t]; bias[320 + t] = ob2[t];
        ((float*)(sm + TV_OFF))[t] = tvec[t];
    }
    __syncthreads();

    const int lane = threadIdx.x & 31;
    const int wid  = threadIdx.x >> 5;
    const int wrow = wid * 32;

    const uint32_t sb = smem_u32(sm);
    const float* tv = (const float*)(sm + TV_OFF);
    const int bn   = (lane & 7) + ((lane >> 4) << 3);
    const int hk8  = (lane >> 3) & 1;
    const int hk16 = lane >> 4;
    const int rn7  = lane & 7;
    const int g7   = (lane >> 2) & 7;
    const int r1 = blockIdx.x * TILE + wrow + (lane >> 2);

    // act-lo smem addressing (swizzled 128B rows, warp-private 32-row region)
    const uint32_t rdB = sb + ACT_OFF + (uint32_t)((wrow + (lane & 15)) * 128);
    const uint32_t wrB = sb + ACT_OFF + (uint32_t)((wrow + (lane >> 2)) * 128 + ((lane & 3) << 2));
    const uint32_t rdP0 = rdB,  rdP1 = rdB + ABUF,  rdP2 = rdB + 2*ABUF;
    const uint32_t wrP0 = wrB,  wrP1 = wrB + ABUF,  wrP2 = wrB + 2*ABUF;

    float tn = tv[lane] * tv[lane] + tv[lane + 32] * tv[lane + 32];
#pragma unroll
    for (int m = 16; m; m >>= 1) tn += __shfl_xor_sync(~0u, tn, m);
    const float tnorm = sqrtf(tn);

    Slot S0, S1, S2;            // H aliases S2's registers (liveness-safe)
    float D[16][4];

    const int q0 = r1, q1 = r1 + 8, q2 = r1 + 16, q3 = r1 + 24;

    gather(S0, wrP0, g7, item, seq[q0*5+0], seq[q1*5+0], seq[q2*5+0], seq[q3*5+0], lane); // e0
    gather(S1, wrP1, g7, item, seq[q0*5+1], seq[q1*5+1], seq[q2*5+1], seq[q3*5+1], lane); // e1
    // n1 = NOT(e1) -> S1/P1   (H=S2 regs, H-lo in P1)
    mlp(D, S2, S1, nullptr, rdP1, 0,    rdP1, wrP1, sb, NW1H, NW1L, RS64,  bias+0,   NW2H, NW2L, bn, hk8, hk16, rn7, g7, lane);
    epi_slot(D, bias + 64, false, S1, wrP1, g7, lane);
    // i5 = AND(e0, n1) -> S0/P0
    mlp(D, S2, S0, &S1,     rdP0, rdP1, rdP0, wrP0, sb, AW1H, AW1L, RS128, bias+128, AW2H, AW2L, bn, hk8, hk16, rn7, g7, lane);
    epi_slot(D, bias + 192, false, S0, wrP0, g7, lane);
    gather(S1, wrP1, g7, item, seq[q0*5+2], seq[q1*5+2], seq[q2*5+2], seq[q3*5+2], lane); // e2
    gather(S2, wrP2, g7, item, seq[q0*5+3], seq[q1*5+3], seq[q2*5+3], seq[q3*5+3], lane); // e3
    // i6 = OR(e2, e3) -> S1/P1   (e3 consumed in layer1 before H overwrites S2)
    mlp(D, S2, S1, &S2,     rdP1, rdP2, rdP1, wrP1, sb, OW1H, OW1L, RS128, bias+256, OW2H, OW2L, bn, hk8, hk16, rn7, g7, lane);
    epi_slot(D, bias + 320, false, S1, wrP1, g7, lane);
    // i7 = AND(i5, i6) -> S0/P0
    mlp(D, S2, S0, &S1,     rdP0, rdP1, rdP0, wrP0, sb, AW1H, AW1L, RS128, bias+128, AW2H, AW2L, bn, hk8, hk16, rn7, g7, lane);
    epi_slot(D, bias + 192, false, S0, wrP0, g7, lane);
    // n7 = NOT(i7) -> S1/P1
    mlp(D, S2, S0, nullptr, rdP0, 0,    rdP1, wrP1, sb, NW1H, NW1L, RS64,  bias+0,   NW2H, NW2L, bn, hk8, hk16, rn7, g7, lane);
    epi_slot(D, bias + 64, false, S1, wrP1, g7, lane);
    gather(S2, wrP2, g7, item, seq[q0*5+4], seq[q1*5+4], seq[q2*5+4], seq[q3*5+4], lane); // e4
    // i8 = OR(n7, e4) -> S0/P0
    mlp(D, S2, S1, &S2,     rdP1, rdP2, rdP0, wrP0, sb, OW1H, OW1L, RS128, bias+256, OW2H, OW2L, bn, hk8, hk16, rn7, g7, lane);
    epi_slot(D, bias + 320, false, S0, wrP0, g7, lane);
    // enc_not = NOT(i8) -> S1/P1
    mlp(D, S2, S0, nullptr, rdP0, 0,    rdP1, wrP1, sb, NW1H, NW1L, RS64,  bias+0,   NW2H, NW2L, bn, hk8, hk16, rn7, g7, lane);
    epi_slot(D, bias + 64, false, S1, wrP1, g7, lane);
    gather(S2, wrP2, g7, item, post[q0], post[q1], post[q2], post[q3], lane);             // pos_e
    // encoded_pos = OR(enc_not, pos_e)   (H uses free buffer P0)
    mlp(D, S2, S1, &S2,     rdP1, rdP2, rdP0, wrP0, sb, OW1H, OW1L, RS128, bias+256, OW2H, OW2L, bn, hk8, hk16, rn7, g7, lane);
    final_epi(D, bias + 320, tv, tnorm, out, r1, lane);
    gather(S2, wrP2, g7, item, negt[q0], negt[q1], negt[q2], negt[q3], lane);             // neg_e
    // encoded_neg = OR(enc_not, neg_e)
    mlp(D, S2, S1, &S2,     rdP1, rdP2, rdP0, wrP0, sb, OW1H, OW1L, RS128, bias+256, OW2H, OW2L, bn, hk8, hk16, rn7, g7, lane);
    final_epi(D, bias + 320, tv, tnorm, out + batch, r1, lane);
}

extern "C" void kernel_launch(void* const* d_in, const int* in_sizes, int n_in,
                              void* d_out, int out_size) {
    const int*   seq   = (const int*)  d_in[0];
    const int*   pos_t = (const int*)  d_in[1];
    const int*   neg_t = (const int*)  d_in[2];
    const float* item  = (const float*)d_in[3];
    const float* tvec  = (const float*)d_in[4];
    const float* nW1 = (const float*)d_in[5];
    const float* nb1 = (const float*)d_in[6];
    const float* nW2 = (const float*)d_in[7];
    const float* nb2 = (const float*)d_in[8];
    const float* aW1 = (const float*)d_in[9];
    const float* ab1 = (const float*)d_in[10];
    const float* aW2 = (const float*)d_in[11];
    const float* ab2 = (const float*)d_in[12];
    const float* oW1 = (const float*)d_in[13];
    const float* ob1 = (const float*)d_in[14];
    const float* oW2 = (const float*)d_in[15];
    const float* ob2 = (const float*)d_in[16];
    float* out = (float*)d_out;

    int batch = in_sizes[1];
    convert_weights<<<128, 256>>>(nW1, nW2, aW1, aW2, oW1, oW2);

    int grid = batch / TILE;
    cudaFuncSetAttribute(logicnet_mma, cudaFuncAttributeMaxDynamicSharedMemorySize, SMEM_REQ);
    logicnet_mma<<<grid, NT, SMEM_REQ>>>(
        seq, pos_t, neg_t, item, tvec,
        nb1, nb2, ab1, ab2, ob1, ob2, out, batch);
}

// round 12
// speedup vs baseline: 1.3242x; 1.1580x over previous
#include <cuda_runtime.h>
#include <cuda_fp16.h>
#include <stdint.h>
#include <math.h>

#define NT   256
#define TILE 128

// packed, XOR-swizzled weight tiles: n-major, row stride = K*2 bytes
#define RS64  128
#define RS128 256

#define NW1H 0
#define NW1L 8192
#define NW2H 16384
#define NW2L 24576
#define AW1H 32768
#define AW1L 49152
#define AW2H 65536
#define AW2L 73728
#define OW1H 81920
#define OW1L 98304
#define OW2H 114688
#define OW2L 122880
#define WBYTES 131072

#define BIAS_OFF WBYTES            // 1536 B (6 x 64 floats)
#define TV_OFF   (BIAS_OFF + 1536)
#define ACT_OFF  (TV_OFF + 256)
#define ABUF     (TILE*128)        // 16384 per lo-buffer (swizzled 128B rows)
#define SMEM_REQ (ACT_OFF + 3*ABUF)   // 182016

#define LO_SCALE   2048.0f
#define LO_INV     4.8828125e-4f   // 2^-11

__device__ __align__(16) unsigned char g_wblob[WBYTES];

// ---------------- helpers ----------------
__device__ __forceinline__ uint32_t smem_u32(const void* p) {
    uint32_t a;
    asm("{ .reg .u64 t; cvta.to.shared.u64 t, %1; cvt.u32.u64 %0, t; }" : "=r"(a) : "l"(p));
    return a;
}

// split x into fp16 hi + fp16 lo' where lo' = (x - hi) * 2^11 (scaled to avoid f16 subnormals)
__device__ __forceinline__ void split2s(float x0, float x1, uint32_t& hi, uint32_t& lo) {
    __half h0 = __float2half_rn(x0), h1 = __float2half_rn(x1);
    __half l0 = __float2half_rn((x0 - __half2float(h0)) * LO_SCALE);
    __half l1 = __float2half_rn((x1 - __half2float(h1)) * LO_SCALE);
    __half2 H = __halves2half2(h0, h1), L = __halves2half2(l0, l1);
    hi = *reinterpret_cast<uint32_t*>(&H);
    lo = *reinterpret_cast<uint32_t*>(&L);
}

#define MMA(D, a0, a1, a2, a3, b0, b1) \
    asm volatile("mma.sync.aligned.m16n8k16.row.col.f32.f16.f16.f32 " \
        "{%0,%1,%2,%3},{%4,%5,%6,%7},{%8,%9},{%0,%1,%2,%3};" \
        : "+f"((D)[0]), "+f"((D)[1]), "+f"((D)[2]), "+f"((D)[3]) \
        : "r"(a0), "r"(a1), "r"(a2), "r"(a3), "r"(b0), "r"(b1))

// fp16-accumulate MMA: D/C are 2 regs of f16x2
#define MMAH(Dc, a0, a1, a2, a3, b0, b1) \
    asm volatile("mma.sync.aligned.m16n8k16.row.col.f16.f16.f16.f16 " \
        "{%0,%1},{%2,%3,%4,%5},{%6,%7},{%0,%1};" \
        : "+r"((Dc)[0]), "+r"((Dc)[1]) \
        : "r"(a0), "r"(a1), "r"(a2), "r"(a3), "r"(b0), "r"(b1))

#define LDSM4(r0, r1, r2, r3, a) \
    asm volatile("ldmatrix.sync.aligned.m8n8.x4.shared.b16 {%0,%1,%2,%3}, [%4];" \
        : "=r"(r0), "=r"(r1), "=r"(r2), "=r"(r3) : "r"(a))

#define STS32(a, v) asm volatile("st.shared.b32 [%0], %1;" :: "r"(a), "r"(v) : "memory")

struct Slot { uint32_t h[16]; };   // activation hi halves (lo' lives in smem)

// ---------------- weight conversion: fp32 -> fp16 hi + scaled lo, packed swizzled ----------------
__global__ void convert_weights(const float* __restrict__ nW1, const float* __restrict__ nW2,
                                const float* __restrict__ aW1, const float* __restrict__ aW2,
                                const float* __restrict__ oW1, const float* __restrict__ oW2) {
    int i = blockIdx.x * blockDim.x + threadIdx.x;
    if (i >= 32768) return;
    int idx = i; const float* src; int hb, lb, rs;
    if (idx < 4096)       { src = nW1; hb = NW1H; lb = NW1L; rs = RS64; }
    else if (idx < 8192)  { idx -= 4096;  src = nW2; hb = NW2H; lb = NW2L; rs = RS64; }
    else if (idx < 16384) { idx -= 8192;  src = aW1; hb = AW1H; lb = AW1L; rs = RS128; }
    else if (idx < 20480) { idx -= 16384; src = aW2; hb = AW2H; lb = AW2L; rs = RS64; }
    else if (idx < 28672) { idx -= 20480; src = oW1; hb = OW1H; lb = OW1L; rs = RS128; }
    else                  { idx -= 28672; src = oW2; hb = OW2H; lb = OW2L; rs = RS64; }
    int k = idx >> 6, n = idx & 63;          // source row-major [K][64]
    float w = src[idx];
    __half h = __float2half_rn(w);
    __half l = __float2half_rn((w - __half2float(h)) * LO_SCALE);
    int off = n * rs + (((k >> 3) ^ (n & 7)) << 4) + (k & 7) * 2;
    *(__half*)(g_wblob + hb + off) = h;
    *(__half*)(g_wblob + lb + off) = l;
}

// ---------------- core compute ----------------
__device__ __forceinline__ void zeroD(float (&D)[8][4], uint32_t (&Dc)[8][2]) {
#pragma unroll
    for (int n = 0; n < 8; n++) {
        D[n][0] = 0.f; D[n][1] = 0.f; D[n][2] = 0.f; D[n][3] = 0.f;
        Dc[n][0] = 0u; Dc[n][1] = 0u;
    }
}

// one K=64 chunk: D += Ah*Wh (f32);  Dc += Al'*Wh + Ah*Wl' (f16 acc, scaled 2^11)
__device__ __forceinline__ void chunk64(float (&D)[8][4], uint32_t (&Dc)[8][2],
                                        const Slot& A, uint32_t aRd,
                                        uint32_t baseH, uint32_t baseL, int rs, int kc0,
                                        int bn, int hk8, int hk16, int rn7) {
#pragma unroll
    for (int kt = 0; kt < 4; kt++) {
        uint32_t xw = (uint32_t)(((kc0 + kt*2 + hk8) ^ rn7) << 4);
        uint32_t xa = (uint32_t)(((kt*2 + hk16) ^ rn7) << 4);
        const uint32_t a0 = A.h[kt*4], a1 = A.h[kt*4+1], a2 = A.h[kt*4+2], a3 = A.h[kt*4+3];
        uint32_t al0, al1, al2, al3;
        LDSM4(al0, al1, al2, al3, aRd + xa);
        uint32_t h[4][4];
#pragma unroll
        for (int np = 0; np < 4; np++) {
            uint32_t ro = (uint32_t)((np*16 + bn) * rs) + xw;
            LDSM4(h[np][0], h[np][1], h[np][2], h[np][3], baseH + ro);
        }
#pragma unroll
        for (int np = 0; np < 4; np++) {
            MMA(D[2*np],   a0, a1, a2, a3, h[np][0], h[np][1]);
            MMA(D[2*np+1], a0, a1, a2, a3, h[np][2], h[np][3]);
        }
#pragma unroll
        for (int np = 0; np < 4; np++) {
            MMAH(Dc[2*np],   al0, al1, al2, al3, h[np][0], h[np][1]);
            MMAH(Dc[2*np+1], al0, al1, al2, al3, h[np][2], h[np][3]);
        }
#pragma unroll
        for (int np = 0; np < 4; np++) {
            uint32_t ro = (uint32_t)((np*16 + bn) * rs) + xw;
            LDSM4(h[np][0], h[np][1], h[np][2], h[np][3], baseL + ro);
        }
#pragma unroll
        for (int np = 0; np < 4; np++) {
            MMAH(Dc[2*np],   a0, a1, a2, a3, h[np][0], h[np][1]);
            MMAH(Dc[2*np+1], a0, a1, a2, a3, h[np][2], h[np][3]);
        }
    }
}

// merge f32 main + scaled f16 correction for one n-tile -> 4 floats
__device__ __forceinline__ void merge4(const float* d, const uint32_t* dc,
                                       float& x0, float& x1, float& x2, float& x3) {
    __half2 p0 = *reinterpret_cast<const __half2*>(&dc[0]);
    __half2 p1 = *reinterpret_cast<const __half2*>(&dc[1]);
    float2 f0 = __half22float2(p0);
    float2 f1 = __half22float2(p1);
    x0 = fmaf(LO_INV, f0.x, d[0]);
    x1 = fmaf(LO_INV, f0.y, d[1]);
    x2 = fmaf(LO_INV, f1.x, d[2]);
    x3 = fmaf(LO_INV, f1.y, d[3]);
}

// D/Dc + bias (+lrelu) -> hi into regs (A-frag layout), scaled lo into smem buffer
__device__ __forceinline__ void epi_slot(float (&D)[8][4], uint32_t (&Dc)[8][2],
                                         const float* __restrict__ bias,
                                         bool lrelu, Slot& S, uint32_t wAddr, int g7, int lane) {
    int c0 = 2 * (lane & 3);
#pragma unroll
    for (int nt = 0; nt < 8; nt++) {
        float b0 = bias[nt*8 + c0], b1 = bias[nt*8 + c0 + 1];
        float x0, x1, x2, x3;
        merge4(D[nt], Dc[nt], x0, x1, x2, x3);
        x0 += b0; x1 += b1; x2 += b0; x3 += b1;
        if (lrelu) {
            x0 = x0 > 0.f ? x0 : 0.01f * x0;
            x1 = x1 > 0.f ? x1 : 0.01f * x1;
            x2 = x2 > 0.f ? x2 : 0.01f * x2;
            x3 = x3 > 0.f ? x3 : 0.01f * x3;
        }
        int r = (nt >> 1) * 4 + (nt & 1) * 2;
        uint32_t lo01, lo23;
        split2s(x0, x1, S.h[r],     lo01);
        split2s(x2, x3, S.h[r + 1], lo23);
        uint32_t a = wAddr + (uint32_t)((nt ^ g7) << 4);
        STS32(a,        lo01);   // row g
        STS32(a + 1024, lo23);   // row g+8
    }
    __syncwarp();
}

// two-layer MLP: leaves raw layer-2 accumulators in D/Dc (bias not applied)
__device__ __forceinline__ void mlp(float (&D)[8][4], uint32_t (&Dc)[8][2], Slot& H,
                                    const Slot& in1, const Slot* in2,
                                    uint32_t a1Rd, uint32_t a2Rd,
                                    uint32_t hRd, uint32_t hWr, uint32_t sb,
                                    uint32_t w1h, uint32_t w1l, int rs1, const float* b1,
                                    uint32_t w2h, uint32_t w2l,
                                    int bn, int hk8, int hk16, int rn7, int g7, int lane) {
    zeroD(D, Dc);
    chunk64(D, Dc, in1, a1Rd, sb + w1h, sb + w1l, rs1, 0, bn, hk8, hk16, rn7);
    if (in2) chunk64(D, Dc, *in2, a2Rd, sb + w1h, sb + w1l, rs1, 8, bn, hk8, hk16, rn7);
    epi_slot(D, Dc, b1, true, H, hWr, g7, lane);
    zeroD(D, Dc);
    chunk64(D, Dc, H, hRd, sb + w2h, sb + w2l, RS64, 0, bn, hk8, hk16, rn7);
}

// gather embedding rows (r1, r2 = r1+8): hi into regs, scaled lo into smem
__device__ __forceinline__ void gather(Slot& S, uint32_t wAddr, int g7,
                                       const float* __restrict__ item,
                                       int i1, int i2, int lane) {
    const float* p1 = item + (size_t)i1 * 64 + 2 * (lane & 3);
    const float* p2 = item + (size_t)i2 * 64 + 2 * (lane & 3);
#pragma unroll
    for (int j = 0; j < 4; j++) {
        float2 a = *(const float2*)(p1 + j * 16);
        float2 b = *(const float2*)(p2 + j * 16);
        float2 c = *(const float2*)(p1 + j * 16 + 8);
        float2 d = *(const float2*)(p2 + j * 16 + 8);
        uint32_t lo;
        uint32_t a0 = wAddr + (uint32_t)(((2*j)     ^ g7) << 4);
        uint32_t a1 = wAddr + (uint32_t)(((2*j + 1) ^ g7) << 4);
        split2s(a.x, a.y, S.h[j*4+0], lo); STS32(a0,        lo);
        split2s(b.x, b.y, S.h[j*4+1], lo); STS32(a0 + 1024, lo);
        split2s(c.x, c.y, S.h[j*4+2], lo); STS32(a1,        lo);
        split2s(d.x, d.y, S.h[j*4+3], lo); STS32(a1 + 1024, lo);
    }
    __syncwarp();
}

// cosine-similarity epilogue on raw layer-2 accumulators
__device__ __forceinline__ void final_epi(float (&D)[8][4], uint32_t (&Dc)[8][2],
                                          const float* __restrict__ bias,
                                          const float* __restrict__ tv, float tnorm,
                                          float* __restrict__ outp, int r1, int lane) {
    int c0 = 2 * (lane & 3);
    float n1 = 0.f, s1 = 0.f, n2 = 0.f, s2 = 0.f;
#pragma unroll
    for (int nt = 0; nt < 8; nt++) {
        float b0 = bias[nt*8 + c0], b1 = bias[nt*8 + c0 + 1];
        float t0 = tv[nt*8 + c0],  t1 = tv[nt*8 + c0 + 1];
        float x0, x1, x2, x3;
        merge4(D[nt], Dc[nt], x0, x1, x2, x3);
        x0 += b0; x1 += b1; x2 += b0; x3 += b1;
        n1 = fmaf(x0, t0, fmaf(x1, t1, n1));  s1 = fmaf(x0, x0, fmaf(x1, x1, s1));
        n2 = fmaf(x2, t0, fmaf(x3, t1, n2));  s2 = fmaf(x2, x2, fmaf(x3, x3, s2));
    }
    n1 += __shfl_xor_sync(~0u, n1, 1); n1 += __shfl_xor_sync(~0u, n1, 2);
    s1 += __shfl_xor_sync(~0u, s1, 1); s1 += __shfl_xor_sync(~0u, s1, 2);
    n2 += __shfl_xor_sync(~0u, n2, 1); n2 += __shfl_xor_sync(~0u, n2, 2);
    s2 += __shfl_xor_sync(~0u, s2, 1); s2 += __shfl_xor_sync(~0u, s2, 2);
    if ((lane & 3) == 0) {
        float dn = fmaxf(tnorm, 1e-8f);
        outp[r1]     = n1 / (fmaxf(sqrtf(s1), 1e-8f) * dn) * 10.0f;
        outp[r1 + 8] = n2 / (fmaxf(sqrtf(s2), 1e-8f) * dn) * 10.0f;
    }
}

// ---------------- main kernel ----------------
__global__ void __launch_bounds__(NT, 1) logicnet_mma(
    const int* __restrict__ seq, const int* __restrict__ post, const int* __restrict__ negt,
    const float* __restrict__ item, const float* __restrict__ tvec,
    const float* __restrict__ nb1, const float* __restrict__ nb2,
    const float* __restrict__ ab1, const float* __restrict__ ab2,
    const float* __restrict__ ob1, const float* __restrict__ ob2,
    float* __restrict__ out, int batch)
{
    extern __shared__ unsigned char sm[];
    {   // stage pre-split, pre-swizzled weights
        const float4* s4 = (const float4*)g_wblob;
        float4* d4 = (float4*)sm;
#pragma unroll 4
        for (int i = threadIdx.x; i < WBYTES / 16; i += NT) d4[i] = s4[i];
    }
    float* bias = (float*)(sm + BIAS_OFF);
    if (threadIdx.x < 64) {
        int t = threadIdx.x;
        bias[t]       = nb1[t]; bias[64 + t]  = nb2[t];
        bias[128 + t] = ab1[t]; bias[192 + t] = ab2[t];
        bias[256 + t] = ob1[t]; bias[320 + t] = ob2[t];
        ((float*)(sm + TV_OFF))[t] = tvec[t];
    }
    __syncthreads();

    const int lane = threadIdx.x & 31;
    const int wid  = threadIdx.x >> 5;
    const int wrow = wid * 16;

    const uint32_t sb = smem_u32(sm);
    const float* tv = (const float*)(sm + TV_OFF);
    const int bn   = (lane & 7) + ((lane >> 4) << 3);
    const int hk8  = (lane >> 3) & 1;
    const int hk16 = lane >> 4;
    const int rn7  = lane & 7;
    const int g7   = (lane >> 2) & 7;
    const int r1 = blockIdx.x * TILE + wrow + (lane >> 2);
    const int r2 = r1 + 8;

    // act-lo smem addressing (swizzled 128B rows, warp-private 16-row region)
    const uint32_t rdB = sb + ACT_OFF + (uint32_t)((wrow + (lane & 15)) * 128);
    const uint32_t wrB = sb + ACT_OFF + (uint32_t)((wrow + (lane >> 2)) * 128 + ((lane & 3) << 2));
    const uint32_t rdP0 = rdB,  rdP1 = rdB + ABUF,  rdP2 = rdB + 2*ABUF;
    const uint32_t wrP0 = wrB,  wrP1 = wrB + ABUF,  wrP2 = wrB + 2*ABUF;

    float tn = tv[lane] * tv[lane] + tv[lane + 32] * tv[lane + 32];
#pragma unroll
    for (int m = 16; m; m >>= 1) tn += __shfl_xor_sync(~0u, tn, m);
    const float tnorm = sqrtf(tn);

    Slot S0, S1, S2, H;
    float D[8][4];
    uint32_t Dc[8][2];

    gather(S0, wrP0, g7, item, seq[r1*5 + 0], seq[r2*5 + 0], lane);   // e0 -> S0/P0
    gather(S1, wrP1, g7, item, seq[r1*5 + 1], seq[r2*5 + 1], lane);   // e1 -> S1/P1
    // n1 = NOT(e1) -> S1/P1
    mlp(D, Dc, H, S1, nullptr, rdP1, 0,    rdP1, wrP1, sb, NW1H, NW1L, RS64,  bias+0,   NW2H, NW2L, bn, hk8, hk16, rn7, g7, lane);
    epi_slot(D, Dc, bias + 64, false, S1, wrP1, g7, lane);
    // i5 = AND(e0, n1) -> S0/P0
    mlp(D, Dc, H, S0, &S1,     rdP0, rdP1, rdP0, wrP0, sb, AW1H, AW1L, RS128, bias+128, AW2H, AW2L, bn, hk8, hk16, rn7, g7, lane);
    epi_slot(D, Dc, bias + 192, false, S0, wrP0, g7, lane);
    gather(S1, wrP1, g7, item, seq[r1*5 + 2], seq[r2*5 + 2], lane);   // e2 -> S1/P1
    gather(S2, wrP2, g7, item, seq[r1*5 + 3], seq[r2*5 + 3], lane);   // e3 -> S2/P2
    // i6 = OR(e2, e3) -> S1/P1
    mlp(D, Dc, H, S1, &S2,     rdP1, rdP2, rdP1, wrP1, sb, OW1H, OW1L, RS128, bias+256, OW2H, OW2L, bn, hk8, hk16, rn7, g7, lane);
    epi_slot(D, Dc, bias + 320, false, S1, wrP1, g7, lane);
    // i7 = AND(i5, i6) -> S0/P0
    mlp(D, Dc, H, S0, &S1,     rdP0, rdP1, rdP0, wrP0, sb, AW1H, AW1L, RS128, bias+128, AW2H, AW2L, bn, hk8, hk16, rn7, g7, lane);
    epi_slot(D, Dc, bias + 192, false, S0, wrP0, g7, lane);
    // n7 = NOT(i7) -> S1/P1
    mlp(D, Dc, H, S0, nullptr, rdP0, 0,    rdP1, wrP1, sb, NW1H, NW1L, RS64,  bias+0,   NW2H, NW2L, bn, hk8, hk16, rn7, g7, lane);
    epi_slot(D, Dc, bias + 64, false, S1, wrP1, g7, lane);
    gather(S2, wrP2, g7, item, seq[r1*5 + 4], seq[r2*5 + 4], lane);   // e4 -> S2/P2
    // i8 = OR(n7, e4) -> S0/P0
    mlp(D, Dc, H, S1, &S2,     rdP1, rdP2, rdP0, wrP0, sb, OW1H, OW1L, RS128, bias+256, OW2H, OW2L, bn, hk8, hk16, rn7, g7, lane);
    epi_slot(D, Dc, bias + 320, false, S0, wrP0, g7, lane);
    // enc_not = NOT(i8) -> S1/P1
    mlp(D, Dc, H, S0, nullptr, rdP0, 0,    rdP1, wrP1, sb, NW1H, NW1L, RS64,  bias+0,   NW2H, NW2L, bn, hk8, hk16, rn7, g7, lane);
    epi_slot(D, Dc, bias + 64, false, S1, wrP1, g7, lane);
    gather(S2, wrP2, g7, item, post[r1], post[r2], lane);             // pos_e -> S2/P2
    // encoded_pos = OR(enc_not, pos_e)   (H uses free buffer P0)
    mlp(D, Dc, H, S1, &S2,     rdP1, rdP2, rdP0, wrP0, sb, OW1H, OW1L, RS128, bias+256, OW2H, OW2L, bn, hk8, hk16, rn7, g7, lane);
    final_epi(D, Dc, bias + 320, tv, tnorm, out, r1, lane);
    gather(S2, wrP2, g7, item, negt[r1], negt[r2], lane);             // neg_e -> S2/P2
    // encoded_neg = OR(enc_not, neg_e)
    mlp(D, Dc, H, S1, &S2,     rdP1, rdP2, rdP0, wrP0, sb, OW1H, OW1L, RS128, bias+256, OW2H, OW2L, bn, hk8, hk16, rn7, g7, lane);
    final_epi(D, Dc, bias + 320, tv, tnorm, out + batch, r1, lane);
}

extern "C" void kernel_launch(void* const* d_in, const int* in_sizes, int n_in,
                              void* d_out, int out_size) {
    const int*   seq   = (const int*)  d_in[0];
    const int*   pos_t = (const int*)  d_in[1];
    const int*   neg_t = (const int*)  d_in[2];
    const float* item  = (const float*)d_in[3];
    const float* tvec  = (const float*)d_in[4];
    const float* nW1 = (const float*)d_in[5];
    const float* nb1 = (const float*)d_in[6];
    const float* nW2 = (const float*)d_in[7];
    const float* nb2 = (const float*)d_in[8];
    const float* aW1 = (const float*)d_in[9];
    const float* ab1 = (const float*)d_in[10];
    const float* aW2 = (const float*)d_in[11];
    const float* ab2 = (const float*)d_in[12];
    const float* oW1 = (const float*)d_in[13];
    const float* ob1 = (const float*)d_in[14];
    const float* oW2 = (const float*)d_in[15];
    const float* ob2 = (const float*)d_in[16];
    float* out = (float*)d_out;

    int batch = in_sizes[1];
    convert_weights<<<128, 256>>>(nW1, nW2, aW1, aW2, oW1, oW2);

    int grid = batch / TILE;
    cudaFuncSetAttribute(logicnet_mma, cudaFuncAttributeMaxDynamicSharedMemorySize, SMEM_REQ);
    logicnet_mma<<<grid, NT, SMEM_REQ>>>(
        seq, pos_t, neg_t, item, tvec,
        nb1, nb2, ab1, ab2, ob1, ob2, out, batch);
}

// round 14
// speedup vs baseline: 1.5255x; 1.1521x over previous
#include <cuda_runtime.h>
#include <cuda_fp16.h>
#include <stdint.h>
#include <math.h>

#define NT   384
#define TILE 192

// packed, XOR-swizzled weight tiles: n-major, row stride = K*2 bytes
#define RS64  128
#define RS128 256

#define NW1H 0
#define NW1L 8192
#define NW2H 16384
#define NW2L 24576
#define AW1H 32768
#define AW1L 49152
#define AW2H 65536
#define AW2L 73728
#define OW1H 81920
#define OW1L 98304
#define OW2H 114688
#define OW2L 122880
#define WBYTES 131072

#define BIAS_OFF WBYTES            // 1536 B (6 x 64 floats)
#define TV_OFF   (BIAS_OFF + 1536)
#define ACT_OFF  (TV_OFF + 256)    // 132864
#define ABUF     (TILE*128)        // 24576 per lo-buffer (swizzled 128B rows)
#define SMEM_REQ (ACT_OFF + 3*ABUF)   // 206592

__device__ __align__(16) unsigned char g_wblob[WBYTES];

// ---------------- helpers ----------------
__device__ __forceinline__ uint32_t smem_u32(const void* p) {
    uint32_t a;
    asm("{ .reg .u64 t; cvta.to.shared.u64 t, %1; cvt.u32.u64 %0, t; }" : "=r"(a) : "l"(p));
    return a;
}

// split (x0,x1) -> fp16 hi pair + fp16 lo pair, packed-cvt form.
// cvt.rn.f16x2.f32 d, a, b  =>  d.hi = cvt(a), d.lo = cvt(b)
__device__ __forceinline__ void split2(float x0, float x1, uint32_t& hi, uint32_t& lo) {
    uint32_t H;
    asm("cvt.rn.f16x2.f32 %0, %1, %2;" : "=r"(H) : "f"(x1), "f"(x0));
    __half2 h2 = *reinterpret_cast<__half2*>(&H);
    float2 hf = __half22float2(h2);
    float l0 = x0 - hf.x;
    float l1 = x1 - hf.y;
    asm("cvt.rn.f16x2.f32 %0, %1, %2;" : "=r"(lo) : "f"(l1), "f"(l0));
    hi = H;
}

#define MMA(D, a0, a1, a2, a3, b0, b1) \
    asm volatile("mma.sync.aligned.m16n8k16.row.col.f32.f16.f16.f32 " \
        "{%0,%1,%2,%3},{%4,%5,%6,%7},{%8,%9},{%0,%1,%2,%3};" \
        : "+f"((D)[0]), "+f"((D)[1]), "+f"((D)[2]), "+f"((D)[3]) \
        : "r"(a0), "r"(a1), "r"(a2), "r"(a3), "r"(b0), "r"(b1))

#define LDSM4(r0, r1, r2, r3, a) \
    asm volatile("ldmatrix.sync.aligned.m8n8.x4.shared.b16 {%0,%1,%2,%3}, [%4];" \
        : "=r"(r0), "=r"(r1), "=r"(r2), "=r"(r3) : "r"(a))

#define STS32(a, v) asm volatile("st.shared.b32 [%0], %1;" :: "r"(a), "r"(v) : "memory")

struct Slot { uint32_t h[16]; };   // activation hi halves (lo lives in smem)

// ---------------- weight conversion: fp32 -> fp16 hi/lo, packed swizzled ----------------
__global__ void convert_weights(const float* __restrict__ nW1, const float* __restrict__ nW2,
                                const float* __restrict__ aW1, const float* __restrict__ aW2,
                                const float* __restrict__ oW1, const float* __restrict__ oW2) {
    int i = blockIdx.x * blockDim.x + threadIdx.x;
    if (i >= 32768) return;
    int idx = i; const float* src; int hb, lb, rs;
    if (idx < 4096)       { src = nW1; hb = NW1H; lb = NW1L; rs = RS64; }
    else if (idx < 8192)  { idx -= 4096;  src = nW2; hb = NW2H; lb = NW2L; rs = RS64; }
    else if (idx < 16384) { idx -= 8192;  src = aW1; hb = AW1H; lb = AW1L; rs = RS128; }
    else if (idx < 20480) { idx -= 16384; src = aW2; hb = AW2H; lb = AW2L; rs = RS64; }
    else if (idx < 28672) { idx -= 20480; src = oW1; hb = OW1H; lb = OW1L; rs = RS128; }
    else                  { idx -= 28672; src = oW2; hb = OW2H; lb = OW2L; rs = RS64; }
    int k = idx >> 6, n = idx & 63;          // source row-major [K][64]
    float w = src[idx];
    __half h = __float2half_rn(w);
    __half l = __float2half_rn(w - __half2float(h));
    // swizzled offset: row n, 16B-chunk (k>>3) XOR (n&7), byte (k&7)*2
    int off = n * rs + (((k >> 3) ^ (n & 7)) << 4) + (k & 7) * 2;
    *(__half*)(g_wblob + hb + off) = h;
    *(__half*)(g_wblob + lb + off) = l;
}

// ---------------- core compute ----------------
__device__ __forceinline__ void zeroD(float (&D)[8][4]) {
#pragma unroll
    for (int n = 0; n < 8; n++)
#pragma unroll
        for (int i = 0; i < 4; i++) D[n][i] = 0.f;
}

// one K=64 chunk: D += Ah*Wh + Al*Wh + Ah*Wl
// kc0: starting 16B-chunk index (0 for k0=0, 8 for k0=64)
__device__ __forceinline__ void chunk64(float (&D)[8][4], const Slot& A, uint32_t aRd,
                                        uint32_t baseH, uint32_t baseL, int rs, int kc0,
                                        int bn, int hk8, int hk16, int rn7) {
#pragma unroll
    for (int kt = 0; kt < 4; kt++) {
        const uint32_t a0 = A.h[kt*4], a1 = A.h[kt*4+1], a2 = A.h[kt*4+2], a3 = A.h[kt*4+3];
        uint32_t xw = (uint32_t)((((kc0 + kt*2 + hk8) ^ rn7)) << 4);
        uint32_t xa = (uint32_t)((((kt*2 + hk16) ^ rn7)) << 4);
        uint32_t al0, al1, al2, al3;
        LDSM4(al0, al1, al2, al3, aRd + xa);
        uint32_t h[4][4];
#pragma unroll
        for (int np = 0; np < 4; np++) {
            uint32_t ro = (uint32_t)((np*16 + bn) * rs) + xw;
            LDSM4(h[np][0], h[np][1], h[np][2], h[np][3], baseH + ro);
        }
#pragma unroll
        for (int np = 0; np < 4; np++) {
            MMA(D[2*np],   a0, a1, a2, a3, h[np][0], h[np][1]);
            MMA(D[2*np+1], a0, a1, a2, a3, h[np][2], h[np][3]);
        }
#pragma unroll
        for (int np = 0; np < 4; np++) {
            MMA(D[2*np],   al0, al1, al2, al3, h[np][0], h[np][1]);
            MMA(D[2*np+1], al0, al1, al2, al3, h[np][2], h[np][3]);
        }
        uint32_t l[4][4];
#pragma unroll
        for (int np = 0; np < 4; np++) {
            uint32_t ro = (uint32_t)((np*16 + bn) * rs) + xw;
            LDSM4(l[np][0], l[np][1], l[np][2], l[np][3], baseL + ro);
        }
#pragma unroll
        for (int np = 0; np < 4; np++) {
            MMA(D[2*np],   a0, a1, a2, a3, l[np][0], l[np][1]);
            MMA(D[2*np+1], a0, a1, a2, a3, l[np][2], l[np][3]);
        }
    }
}

// D + bias (+lrelu) -> hi into regs (A-frag layout), lo into swizzled smem buffer
__device__ __forceinline__ void epi_slot(float (&D)[8][4], const float* __restrict__ bias,
                                         bool lrelu, Slot& S, uint32_t wAddr, int g7, int lane) {
    int c0 = 2 * (lane & 3);
#pragma unroll
    for (int nt = 0; nt < 8; nt++) {
        float b0 = bias[nt*8 + c0], b1 = bias[nt*8 + c0 + 1];
        float x0 = D[nt][0] + b0, x1 = D[nt][1] + b1;
        float x2 = D[nt][2] + b0, x3 = D[nt][3] + b1;
        if (lrelu) {
            x0 = fmaxf(x0, 0.01f * x0);
            x1 = fmaxf(x1, 0.01f * x1);
            x2 = fmaxf(x2, 0.01f * x2);
            x3 = fmaxf(x3, 0.01f * x3);
        }
        int r = (nt >> 1) * 4 + (nt & 1) * 2;
        uint32_t lo01, lo23;
        split2(x0, x1, S.h[r],     lo01);
        split2(x2, x3, S.h[r + 1], lo23);
        uint32_t a = wAddr + (uint32_t)(((nt ^ g7)) << 4);
        STS32(a,        lo01);   // row g
        STS32(a + 1024, lo23);   // row g+8
    }
    __syncwarp();
}

// two-layer MLP: leaves layer-2 raw accumulators in D (bias not applied)
// H-lo shares the DST buffer (hWr/hRd point at the dst slot's lo buffer)
__device__ __forceinline__ void mlp(float (&D)[8][4], Slot& H,
                                    const Slot& in1, const Slot* in2,
                                    uint32_t a1Rd, uint32_t a2Rd,
                                    uint32_t hRd, uint32_t hWr, uint32_t sb,
                                    uint32_t w1h, uint32_t w1l, int rs1, const float* b1,
                                    uint32_t w2h, uint32_t w2l,
                                    int bn, int hk8, int hk16, int rn7, int g7, int lane) {
    zeroD(D);
    chunk64(D, in1, a1Rd, sb + w1h, sb + w1l, rs1, 0, bn, hk8, hk16, rn7);
    if (in2) chunk64(D, *in2, a2Rd, sb + w1h, sb + w1l, rs1, 8, bn, hk8, hk16, rn7);
    epi_slot(D, b1, true, H, hWr, g7, lane);
    zeroD(D);
    chunk64(D, H, hRd, sb + w2h, sb + w2l, RS64, 0, bn, hk8, hk16, rn7);
}

// gather embedding rows (r1, r2 = r1+8): hi into regs, lo into swizzled smem buffer
__device__ __forceinline__ void gather(Slot& S, uint32_t wAddr, int g7,
                                       const float* __restrict__ item,
                                       int i1, int i2, int lane) {
    const float* p1 = item + (size_t)i1 * 64 + 2 * (lane & 3);
    const float* p2 = item + (size_t)i2 * 64 + 2 * (lane & 3);
#pragma unroll
    for (int j = 0; j < 4; j++) {
        float2 a = *(const float2*)(p1 + j * 16);
        float2 b = *(const float2*)(p2 + j * 16);
        float2 c = *(const float2*)(p1 + j * 16 + 8);
        float2 d = *(const float2*)(p2 + j * 16 + 8);
        uint32_t lo;
        uint32_t a0 = wAddr + (uint32_t)((((2*j)     ^ g7)) << 4);
        uint32_t a1 = wAddr + (uint32_t)((((2*j + 1) ^ g7)) << 4);
        split2(a.x, a.y, S.h[j*4+0], lo); STS32(a0,        lo);
        split2(b.x, b.y, S.h[j*4+1], lo); STS32(a0 + 1024, lo);
        split2(c.x, c.y, S.h[j*4+2], lo); STS32(a1,        lo);
        split2(d.x, d.y, S.h[j*4+3], lo); STS32(a1 + 1024, lo);
    }
    __syncwarp();
}

// cosine-similarity epilogue on raw layer-2 accumulators
__device__ __forceinline__ void final_epi(float (&D)[8][4], const float* __restrict__ bias,
                                          const float* __restrict__ tv, float tnorm,
                                          float* __restrict__ outp, int r1, int lane) {
    int c0 = 2 * (lane & 3);
    float n1 = 0.f, s1 = 0.f, n2 = 0.f, s2 = 0.f;
#pragma unroll
    for (int nt = 0; nt < 8; nt++) {
        float b0 = bias[nt*8 + c0], b1 = bias[nt*8 + c0 + 1];
        float t0 = tv[nt*8 + c0],  t1 = tv[nt*8 + c0 + 1];
        float x0 = D[nt][0] + b0, x1 = D[nt][1] + b1;
        float x2 = D[nt][2] + b0, x3 = D[nt][3] + b1;
        n1 = fmaf(x0, t0, fmaf(x1, t1, n1));  s1 = fmaf(x0, x0, fmaf(x1, x1, s1));
        n2 = fmaf(x2, t0, fmaf(x3, t1, n2));  s2 = fmaf(x2, x2, fmaf(x3, x3, s2));
    }
    n1 += __shfl_xor_sync(~0u, n1, 1); n1 += __shfl_xor_sync(~0u, n1, 2);
    s1 += __shfl_xor_sync(~0u, s1, 1); s1 += __shfl_xor_sync(~0u, s1, 2);
    n2 += __shfl_xor_sync(~0u, n2, 1); n2 += __shfl_xor_sync(~0u, n2, 2);
    s2 += __shfl_xor_sync(~0u, s2, 1); s2 += __shfl_xor_sync(~0u, s2, 2);
    if ((lane & 3) == 0) {
        float dn = fmaxf(tnorm, 1e-8f);
        outp[r1]     = n1 / (fmaxf(sqrtf(s1), 1e-8f) * dn) * 10.0f;
        outp[r1 + 8] = n2 / (fmaxf(sqrtf(s2), 1e-8f) * dn) * 10.0f;
    }
}

// ---------------- main kernel ----------------
__global__ void __launch_bounds__(NT, 1) logicnet_mma(
    const int* __restrict__ seq, const int* __restrict__ post, const int* __restrict__ negt,
    const float* __restrict__ item, const float* __restrict__ tvec,
    const float* __restrict__ nb1, const float* __restrict__ nb2,
    const float* __restrict__ ab1, const float* __restrict__ ab2,
    const float* __restrict__ ob1, const float* __restrict__ ob2,
    float* __restrict__ out, int batch)
{
    extern __shared__ unsigned char sm[];
    const int lane = threadIdx.x & 31;
    const int wid  = threadIdx.x >> 5;
    const int wrow = wid * 16;
    const int base0 = blockIdx.x * TILE + wrow;

    // L2-prefetch all 7 embedding gathers for this warp (indices known up front)
    if (base0 < batch) {
        int gr = base0 + (lane >> 1);
        int half = lane & 1;
#pragma unroll
        for (int g = 0; g < 7; g++) {
            int idx = (g < 5) ? seq[gr * 5 + g] : (g == 5 ? post[gr] : negt[gr]);
            const float* ad = item + (size_t)idx * 64 + half * 32;
            asm volatile("prefetch.global.L2 [%0];" :: "l"(ad));
        }
    }

    {   // stage pre-split, pre-swizzled weights
        const float4* s4 = (const float4*)g_wblob;
        float4* d4 = (float4*)sm;
        for (int i = threadIdx.x; i < WBYTES / 16; i += NT) d4[i] = s4[i];
    }
    float* bias = (float*)(sm + BIAS_OFF);
    if (threadIdx.x < 64) {
        int t = threadIdx.x;
        bias[t]       = nb1[t]; bias[64 + t]  = nb2[t];
        bias[128 + t] = ab1[t]; bias[192 + t] = ab2[t];
        bias[256 + t] = ob1[t]; bias[320 + t] = ob2[t];
        ((float*)(sm + TV_OFF))[t] = tvec[t];
    }
    __syncthreads();

    if (base0 >= batch) return;   // tail-CTA inactive warps

    const uint32_t sb = smem_u32(sm);
    const float* tv = (const float*)(sm + TV_OFF);
    const int bn   = (lane & 7) + ((lane >> 4) << 3);
    const int hk8  = (lane >> 3) & 1;
    const int hk16 = lane >> 4;
    const int rn7  = lane & 7;
    const int g7   = (lane >> 2) & 7;
    const int r1 = base0 + (lane >> 2);
    const int r2 = r1 + 8;

    // act-lo smem addressing (swizzled 128B rows, warp-private 16-row region)
    const uint32_t rdB = sb + ACT_OFF + (uint32_t)((wrow + (lane & 15)) * 128);
    const uint32_t wrB = sb + ACT_OFF + (uint32_t)((wrow + (lane >> 2)) * 128 + ((lane & 3) << 2));
    const uint32_t rdP0 = rdB,            rdP1 = rdB + ABUF,  rdP2 = rdB + 2*ABUF;
    const uint32_t wrP0 = wrB,            wrP1 = wrB + ABUF,  wrP2 = wrB + 2*ABUF;

    float tn = tv[lane] * tv[lane] + tv[lane + 32] * tv[lane + 32];
#pragma unroll
    for (int m = 16; m; m >>= 1) tn += __shfl_xor_sync(~0u, tn, m);
    const float tnorm = sqrtf(tn);

    Slot S0, S1, S2, H;
    float D[8][4];

    gather(S0, wrP0, g7, item, seq[r1*5 + 0], seq[r2*5 + 0], lane);   // e0 -> S0/P0
    gather(S1, wrP1, g7, item, seq[r1*5 + 1], seq[r2*5 + 1], lane);   // e1 -> S1/P1
    // n1 = NOT(e1) -> S1/P1
    mlp(D, H, S1, nullptr, rdP1, 0,    rdP1, wrP1, sb, NW1H, NW1L, RS64,  bias+0,   NW2H, NW2L, bn, hk8, hk16, rn7, g7, lane);
    epi_slot(D, bias + 64, false, S1, wrP1, g7, lane);
    // i5 = AND(e0, n1) -> S0/P0
    mlp(D, H, S0, &S1,     rdP0, rdP1, rdP0, wrP0, sb, AW1H, AW1L, RS128, bias+128, AW2H, AW2L, bn, hk8, hk16, rn7, g7, lane);
    epi_slot(D, bias + 192, false, S0, wrP0, g7, lane);
    gather(S1, wrP1, g7, item, seq[r1*5 + 2], seq[r2*5 + 2], lane);   // e2 -> S1/P1
    gather(S2, wrP2, g7, item, seq[r1*5 + 3], seq[r2*5 + 3], lane);   // e3 -> S2/P2
    // i6 = OR(e2, e3) -> S1/P1
    mlp(D, H, S1, &S2,     rdP1, rdP2, rdP1, wrP1, sb, OW1H, OW1L, RS128, bias+256, OW2H, OW2L, bn, hk8, hk16, rn7, g7, lane);
    epi_slot(D, bias + 320, false, S1, wrP1, g7, lane);
    // i7 = AND(i5, i6) -> S0/P0
    mlp(D, H, S0, &S1,     rdP0, rdP1, rdP0, wrP0, sb, AW1H, AW1L, RS128, bias+128, AW2H, AW2L, bn, hk8, hk16, rn7, g7, lane);
    epi_slot(D, bias + 192, false, S0, wrP0, g7, lane);
    // n7 = NOT(i7) -> S1/P1
    mlp(D, H, S0, nullptr, rdP0, 0,    rdP1, wrP1, sb, NW1H, NW1L, RS64,  bias+0,   NW2H, NW2L, bn, hk8, hk16, rn7, g7, lane);
    epi_slot(D, bias + 64, false, S1, wrP1, g7, lane);
    gather(S2, wrP2, g7, item, seq[r1*5 + 4], seq[r2*5 + 4], lane);   // e4 -> S2/P2
    // i8 = OR(n7, e4) -> S0/P0
    mlp(D, H, S1, &S2,     rdP1, rdP2, rdP0, wrP0, sb, OW1H, OW1L, RS128, bias+256, OW2H, OW2L, bn, hk8, hk16, rn7, g7, lane);
    epi_slot(D, bias + 320, false, S0, wrP0, g7, lane);
    // enc_not = NOT(i8) -> S1/P1
    mlp(D, H, S0, nullptr, rdP0, 0,    rdP1, wrP1, sb, NW1H, NW1L, RS64,  bias+0,   NW2H, NW2L, bn, hk8, hk16, rn7, g7, lane);
    epi_slot(D, bias + 64, false, S1, wrP1, g7, lane);
    gather(S2, wrP2, g7, item, post[r1], post[r2], lane);             // pos_e -> S2/P2
    // encoded_pos = OR(enc_not, pos_e)   (H uses free buffer P0)
    mlp(D, H, S1, &S2,     rdP1, rdP2, rdP0, wrP0, sb, OW1H, OW1L, RS128, bias+256, OW2H, OW2L, bn, hk8, hk16, rn7, g7, lane);
    final_epi(D, bias + 320, tv, tnorm, out, r1, lane);
    gather(S2, wrP2, g7, item, negt[r1], negt[r2], lane);             // neg_e -> S2/P2
    // encoded_neg = OR(enc_not, neg_e)
    mlp(D, H, S1, &S2,     rdP1, rdP2, rdP0, wrP0, sb, OW1H, OW1L, RS128, bias+256, OW2H, OW2L, bn, hk8, hk16, rn7, g7, lane);
    final_epi(D, bias + 320, tv, tnorm, out + batch, r1, lane);
}

extern "C" void kernel_launch(void* const* d_in, const int* in_sizes, int n_in,
                              void* d_out, int out_size) {
    const int*   seq   = (const int*)  d_in[0];
    const int*   pos_t = (const int*)  d_in[1];
    const int*   neg_t = (const int*)  d_in[2];
    const float* item  = (const float*)d_in[3];
    const float* tvec  = (const float*)d_in[4];
    const float* nW1 = (const float*)d_in[5];
    const float* nb1 = (const float*)d_in[6];
    const float* nW2 = (const float*)d_in[7];
    const float* nb2 = (const float*)d_in[8];
    const float* aW1 = (const float*)d_in[9];
    const float* ab1 = (const float*)d_in[10];
    const float* aW2 = (const float*)d_in[11];
    const float* ab2 = (const float*)d_in[12];
    const float* oW1 = (const float*)d_in[13];
    const float* ob1 = (const float*)d_in[14];
    const float* oW2 = (const float*)d_in[15];
    const float* ob2 = (const float*)d_in[16];
    float* out = (float*)d_out;

    int batch = in_sizes[1];
    convert_weights<<<128, 256>>>(nW1, nW2, aW1, aW2, oW1, oW2);

    int grid = (batch + TILE - 1) / TILE;
    cudaFuncSetAttribute(logicnet_mma, cudaFuncAttributeMaxDynamicSharedMemorySize, SMEM_REQ);
    logicnet_mma<<<grid, NT, SMEM_REQ>>>(
        seq, pos_t, neg_t, item, tvec,
        nb1, nb2, ab1, ab2, ob1, ob2, out, batch);
}

// round 16
// speedup vs baseline: 1.5648x; 1.0258x over previous
#include <cuda_runtime.h>
#include <cuda_fp16.h>
#include <stdint.h>
#include <math.h>

#define NT   384
#define TILE 192

// packed, XOR-swizzled weight tiles: n-major, row stride = K*2 bytes
#define RS64  128
#define RS128 256

#define NW1H 0
#define NW1L 8192
#define NW2H 16384
#define NW2L 24576
#define AW1H 32768
#define AW1L 49152
#define AW2H 65536
#define AW2L 73728
#define OW1H 81920
#define OW1L 98304
#define OW2H 114688
#define OW2L 122880
#define WBYTES 131072

#define BIAS_OFF WBYTES            // 1536 B (6 x 64 floats)
#define TV_OFF   (BIAS_OFF + 1536)
#define ACT_OFF  (TV_OFF + 256)    // 132864
#define ABUF     (TILE*128)        // 24576 per lo-buffer (swizzled 128B rows)
#define SMEM_REQ (ACT_OFF + 3*ABUF)   // 206592

#define STAGGER_CYC 3500ull

__device__ __align__(16) unsigned char g_wblob[WBYTES];

// ---------------- helpers ----------------
__device__ __forceinline__ uint32_t smem_u32(const void* p) {
    uint32_t a;
    asm("{ .reg .u64 t; cvta.to.shared.u64 t, %1; cvt.u32.u64 %0, t; }" : "=r"(a) : "l"(p));
    return a;
}
__device__ __forceinline__ unsigned long long rdclock() {
    unsigned long long c;
    asm volatile("mov.u64 %0, %%clock64;" : "=l"(c));
    return c;
}

// split (x0,x1) -> fp16 hi pair + fp16 lo pair, packed-cvt form.
__device__ __forceinline__ void split2(float x0, float x1, uint32_t& hi, uint32_t& lo) {
    uint32_t H;
    asm("cvt.rn.f16x2.f32 %0, %1, %2;" : "=r"(H) : "f"(x1), "f"(x0));
    __half2 h2 = *reinterpret_cast<__half2*>(&H);
    float2 hf = __half22float2(h2);
    float l0 = x0 - hf.x;
    float l1 = x1 - hf.y;
    asm("cvt.rn.f16x2.f32 %0, %1, %2;" : "=r"(lo) : "f"(l1), "f"(l0));
    hi = H;
}

#define MMA(D, a0, a1, a2, a3, b0, b1) \
    asm volatile("mma.sync.aligned.m16n8k16.row.col.f32.f16.f16.f32 " \
        "{%0,%1,%2,%3},{%4,%5,%6,%7},{%8,%9},{%0,%1,%2,%3};" \
        : "+f"((D)[0]), "+f"((D)[1]), "+f"((D)[2]), "+f"((D)[3]) \
        : "r"(a0), "r"(a1), "r"(a2), "r"(a3), "r"(b0), "r"(b1))

#define LDSM4(r0, r1, r2, r3, a) \
    asm volatile("ldmatrix.sync.aligned.m8n8.x4.shared.b16 {%0,%1,%2,%3}, [%4];" \
        : "=r"(r0), "=r"(r1), "=r"(r2), "=r"(r3) : "r"(a))

#define STS32(a, v) asm volatile("st.shared.b32 [%0], %1;" :: "r"(a), "r"(v) : "memory")

struct Slot { uint32_t h[16]; };   // activation hi halves (lo lives in smem)

// ---------------- weight conversion: fp32 -> fp16 hi/lo, packed swizzled ----------------
__global__ void convert_weights(const float* __restrict__ nW1, const float* __restrict__ nW2,
                                const float* __restrict__ aW1, const float* __restrict__ aW2,
                                const float* __restrict__ oW1, const float* __restrict__ oW2) {
    int i = blockIdx.x * blockDim.x + threadIdx.x;
    if (i >= 32768) return;
    int idx = i; const float* src; int hb, lb, rs;
    if (idx < 4096)       { src = nW1; hb = NW1H; lb = NW1L; rs = RS64; }
    else if (idx < 8192)  { idx -= 4096;  src = nW2; hb = NW2H; lb = NW2L; rs = RS64; }
    else if (idx < 16384) { idx -= 8192;  src = aW1; hb = AW1H; lb = AW1L; rs = RS128; }
    else if (idx < 20480) { idx -= 16384; src = aW2; hb = AW2H; lb = AW2L; rs = RS64; }
    else if (idx < 28672) { idx -= 20480; src = oW1; hb = OW1H; lb = OW1L; rs = RS128; }
    else                  { idx -= 28672; src = oW2; hb = OW2H; lb = OW2L; rs = RS64; }
    int k = idx >> 6, n = idx & 63;          // source row-major [K][64]
    float w = src[idx];
    __half h = __float2half_rn(w);
    __half l = __float2half_rn(w - __half2float(h));
    int off = n * rs + (((k >> 3) ^ (n & 7)) << 4) + (k & 7) * 2;
    *(__half*)(g_wblob + hb + off) = h;
    *(__half*)(g_wblob + lb + off) = l;
}

// ---------------- core compute ----------------
__device__ __forceinline__ void zeroD(float (&D)[8][4]) {
#pragma unroll
    for (int n = 0; n < 8; n++)
#pragma unroll
        for (int i = 0; i < 4; i++) D[n][i] = 0.f;
}

// one K=64 chunk: D += Ah*Wh + Al*Wh + Ah*Wl
__device__ __forceinline__ void chunk64(float (&D)[8][4], const Slot& A, uint32_t aRd,
                                        uint32_t baseH, uint32_t baseL, int rs, int kc0,
                                        int bn, int hk8, int hk16, int rn7) {
#pragma unroll
    for (int kt = 0; kt < 4; kt++) {
        const uint32_t a0 = A.h[kt*4], a1 = A.h[kt*4+1], a2 = A.h[kt*4+2], a3 = A.h[kt*4+3];
        uint32_t xw = (uint32_t)((((kc0 + kt*2 + hk8) ^ rn7)) << 4);
        uint32_t xa = (uint32_t)((((kt*2 + hk16) ^ rn7)) << 4);
        uint32_t al0, al1, al2, al3;
        LDSM4(al0, al1, al2, al3, aRd + xa);
        uint32_t h[4][4];
#pragma unroll
        for (int np = 0; np < 4; np++) {
            uint32_t ro = (uint32_t)((np*16 + bn) * rs) + xw;
            LDSM4(h[np][0], h[np][1], h[np][2], h[np][3], baseH + ro);
        }
#pragma unroll
        for (int np = 0; np < 4; np++) {
            MMA(D[2*np],   a0, a1, a2, a3, h[np][0], h[np][1]);
            MMA(D[2*np+1], a0, a1, a2, a3, h[np][2], h[np][3]);
        }
#pragma unroll
        for (int np = 0; np < 4; np++) {
            MMA(D[2*np],   al0, al1, al2, al3, h[np][0], h[np][1]);
            MMA(D[2*np+1], al0, al1, al2, al3, h[np][2], h[np][3]);
        }
        uint32_t l[4][4];
#pragma unroll
        for (int np = 0; np < 4; np++) {
            uint32_t ro = (uint32_t)((np*16 + bn) * rs) + xw;
            LDSM4(l[np][0], l[np][1], l[np][2], l[np][3], baseL + ro);
        }
#pragma unroll
        for (int np = 0; np < 4; np++) {
            MMA(D[2*np],   a0, a1, a2, a3, l[np][0], l[np][1]);
            MMA(D[2*np+1], a0, a1, a2, a3, l[np][2], l[np][3]);
        }
    }
}

// D + bias (+lrelu) -> hi into regs (A-frag layout), lo into swizzled smem buffer
__device__ __forceinline__ void epi_slot(float (&D)[8][4], const float* __restrict__ bias,
                                         bool lrelu, Slot& S, uint32_t wAddr, int g7, int lane) {
    int c0 = 2 * (lane & 3);
#pragma unroll
    for (int nt = 0; nt < 8; nt++) {
        float b0 = bias[nt*8 + c0], b1 = bias[nt*8 + c0 + 1];
        float x0 = D[nt][0] + b0, x1 = D[nt][1] + b1;
        float x2 = D[nt][2] + b0, x3 = D[nt][3] + b1;
        if (lrelu) {
            x0 = fmaxf(x0, 0.01f * x0);
            x1 = fmaxf(x1, 0.01f * x1);
            x2 = fmaxf(x2, 0.01f * x2);
            x3 = fmaxf(x3, 0.01f * x3);
        }
        int r = (nt >> 1) * 4 + (nt & 1) * 2;
        uint32_t lo01, lo23;
        split2(x0, x1, S.h[r],     lo01);
        split2(x2, x3, S.h[r + 1], lo23);
        uint32_t a = wAddr + (uint32_t)(((nt ^ g7)) << 4);
        STS32(a,        lo01);   // row g
        STS32(a + 1024, lo23);   // row g+8
    }
    __syncwarp();
}

// two-layer MLP: leaves layer-2 raw accumulators in D (bias not applied)
__device__ __forceinline__ void mlp(float (&D)[8][4], Slot& H,
                                    const Slot& in1, const Slot* in2,
                                    uint32_t a1Rd, uint32_t a2Rd,
                                    uint32_t hRd, uint32_t hWr, uint32_t sb,
                                    uint32_t w1h, uint32_t w1l, int rs1, const float* b1,
                                    uint32_t w2h, uint32_t w2l,
                                    int bn, int hk8, int hk16, int rn7, int g7, int lane) {
    zeroD(D);
    chunk64(D, in1, a1Rd, sb + w1h, sb + w1l, rs1, 0, bn, hk8, hk16, rn7);
    if (in2) chunk64(D, *in2, a2Rd, sb + w1h, sb + w1l, rs1, 8, bn, hk8, hk16, rn7);
    epi_slot(D, b1, true, H, hWr, g7, lane);
    zeroD(D);
    chunk64(D, H, hRd, sb + w2h, sb + w2l, RS64, 0, bn, hk8, hk16, rn7);
}

// gather embedding rows (r1, r2 = r1+8): hi into regs, lo into swizzled smem buffer
__device__ __forceinline__ void gather(Slot& S, uint32_t wAddr, int g7,
                                       const float* __restrict__ item,
                                       int i1, int i2, int lane) {
    const float* p1 = item + (size_t)i1 * 64 + 2 * (lane & 3);
    const float* p2 = item + (size_t)i2 * 64 + 2 * (lane & 3);
#pragma unroll
    for (int j = 0; j < 4; j++) {
        float2 a = *(const float2*)(p1 + j * 16);
        float2 b = *(const float2*)(p2 + j * 16);
        float2 c = *(const float2*)(p1 + j * 16 + 8);
        float2 d = *(const float2*)(p2 + j * 16 + 8);
        uint32_t lo;
        uint32_t a0 = wAddr + (uint32_t)((((2*j)     ^ g7)) << 4);
        uint32_t a1 = wAddr + (uint32_t)((((2*j + 1) ^ g7)) << 4);
        split2(a.x, a.y, S.h[j*4+0], lo); STS32(a0,        lo);
        split2(b.x, b.y, S.h[j*4+1], lo); STS32(a0 + 1024, lo);
        split2(c.x, c.y, S.h[j*4+2], lo); STS32(a1,        lo);
        split2(d.x, d.y, S.h[j*4+3], lo); STS32(a1 + 1024, lo);
    }
    __syncwarp();
}

// cosine-similarity epilogue on raw layer-2 accumulators
__device__ __forceinline__ void final_epi(float (&D)[8][4], const float* __restrict__ bias,
                                          const float* __restrict__ tv, float tnorm,
                                          float* __restrict__ outp, int r1, int lane) {
    int c0 = 2 * (lane & 3);
    float n1 = 0.f, s1 = 0.f, n2 = 0.f, s2 = 0.f;
#pragma unroll
    for (int nt = 0; nt < 8; nt++) {
        float b0 = bias[nt*8 + c0], b1 = bias[nt*8 + c0 + 1];
        float t0 = tv[nt*8 + c0],  t1 = tv[nt*8 + c0 + 1];
        float x0 = D[nt][0] + b0, x1 = D[nt][1] + b1;
        float x2 = D[nt][2] + b0, x3 = D[nt][3] + b1;
        n1 = fmaf(x0, t0, fmaf(x1, t1, n1));  s1 = fmaf(x0, x0, fmaf(x1, x1, s1));
        n2 = fmaf(x2, t0, fmaf(x3, t1, n2));  s2 = fmaf(x2, x2, fmaf(x3, x3, s2));
    }
    n1 += __shfl_xor_sync(~0u, n1, 1); n1 += __shfl_xor_sync(~0u, n1, 2);
    s1 += __shfl_xor_sync(~0u, s1, 1); s1 += __shfl_xor_sync(~0u, s1, 2);
    n2 += __shfl_xor_sync(~0u, n2, 1); n2 += __shfl_xor_sync(~0u, n2, 2);
    s2 += __shfl_xor_sync(~0u, s2, 1); s2 += __shfl_xor_sync(~0u, s2, 2);
    if ((lane & 3) == 0) {
        float dn = fmaxf(tnorm, 1e-8f);
        outp[r1]     = n1 / (fmaxf(sqrtf(s1), 1e-8f) * dn) * 10.0f;
        outp[r1 + 8] = n2 / (fmaxf(sqrtf(s2), 1e-8f) * dn) * 10.0f;
    }
}

// ---------------- main kernel ----------------
__global__ void __launch_bounds__(NT, 1) logicnet_mma(
    const int* __restrict__ seq, const int* __restrict__ post, const int* __restrict__ negt,
    const float* __restrict__ item, const float* __restrict__ tvec,
    const float* __restrict__ nb1, const float* __restrict__ nb2,
    const float* __restrict__ ab1, const float* __restrict__ ab2,
    const float* __restrict__ ob1, const float* __restrict__ ob2,
    float* __restrict__ out, int batch)
{
    extern __shared__ unsigned char sm[];
    const int lane = threadIdx.x & 31;
    const int wid  = threadIdx.x >> 5;
    const int wrow = wid * 16;
    const int base0 = blockIdx.x * TILE + wrow;

    // L2-prefetch all 7 embedding gathers for this warp (indices known up front)
    if (base0 < batch) {
        int gr = base0 + (lane >> 1);
        int half = lane & 1;
#pragma unroll
        for (int g = 0; g < 7; g++) {
            int idx = (g < 5) ? seq[gr * 5 + g] : (g == 5 ? post[gr] : negt[gr]);
            const float* ad = item + (size_t)idx * 64 + half * 32;
            asm volatile("prefetch.global.L2 [%0];" :: "l"(ad));
        }
    }

    {   // stage pre-split, pre-swizzled weights
        const float4* s4 = (const float4*)g_wblob;
        float4* d4 = (float4*)sm;
        for (int i = threadIdx.x; i < WBYTES / 16; i += NT) d4[i] = s4[i];
    }
    float* bias = (float*)(sm + BIAS_OFF);
    if (threadIdx.x < 64) {
        int t = threadIdx.x;
        bias[t]       = nb1[t]; bias[64 + t]  = nb2[t];
        bias[128 + t] = ab1[t]; bias[192 + t] = ab2[t];
        bias[256 + t] = ob1[t]; bias[320 + t] = ob2[t];
        ((float*)(sm + TV_OFF))[t] = tvec[t];
    }
    __syncthreads();

    if (base0 >= batch) return;   // tail-CTA inactive warps

    // ---- de-phase warps within each SMSP (wid%4 = SMSP; wid>>2 = slot in SMSP) ----
    {
        unsigned long long dly = (unsigned long long)(wid >> 2) * STAGGER_CYC;
        if (dly) {
            unsigned long long t0 = rdclock();
            while (rdclock() - t0 < dly) { }
        }
    }

    const uint32_t sb = smem_u32(sm);
    const float* tv = (const float*)(sm + TV_OFF);
    const int bn   = (lane & 7) + ((lane >> 4) << 3);
    const int hk8  = (lane >> 3) & 1;
    const int hk16 = lane >> 4;
    const int rn7  = lane & 7;
    const int g7   = (lane >> 2) & 7;
    const int r1 = base0 + (lane >> 2);
    const int r2 = r1 + 8;

    // act-lo smem addressing (swizzled 128B rows, warp-private 16-row region)
    const uint32_t rdB = sb + ACT_OFF + (uint32_t)((wrow + (lane & 15)) * 128);
    const uint32_t wrB = sb + ACT_OFF + (uint32_t)((wrow + (lane >> 2)) * 128 + ((lane & 3) << 2));
    const uint32_t rdP0 = rdB,            rdP1 = rdB + ABUF,  rdP2 = rdB + 2*ABUF;
    const uint32_t wrP0 = wrB,            wrP1 = wrB + ABUF,  wrP2 = wrB + 2*ABUF;

    float tn = tv[lane] * tv[lane] + tv[lane + 32] * tv[lane + 32];
#pragma unroll
    for (int m = 16; m; m >>= 1) tn += __shfl_xor_sync(~0u, tn, m);
    const float tnorm = sqrtf(tn);

    Slot S0, S1, S2, H;
    float D[8][4];

    gather(S0, wrP0, g7, item, seq[r1*5 + 0], seq[r2*5 + 0], lane);   // e0 -> S0/P0
    gather(S1, wrP1, g7, item, seq[r1*5 + 1], seq[r2*5 + 1], lane);   // e1 -> S1/P1
    // n1 = NOT(e1) -> S1/P1
    mlp(D, H, S1, nullptr, rdP1, 0,    rdP1, wrP1, sb, NW1H, NW1L, RS64,  bias+0,   NW2H, NW2L, bn, hk8, hk16, rn7, g7, lane);
    epi_slot(D, bias + 64, false, S1, wrP1, g7, lane);
    // i5 = AND(e0, n1) -> S0/P0
    mlp(D, H, S0, &S1,     rdP0, rdP1, rdP0, wrP0, sb, AW1H, AW1L, RS128, bias+128, AW2H, AW2L, bn, hk8, hk16, rn7, g7, lane);
    epi_slot(D, bias + 192, false, S0, wrP0, g7, lane);
    gather(S1, wrP1, g7, item, seq[r1*5 + 2], seq[r2*5 + 2], lane);   // e2 -> S1/P1
    gather(S2, wrP2, g7, item, seq[r1*5 + 3], seq[r2*5 + 3], lane);   // e3 -> S2/P2
    // i6 = OR(e2, e3) -> S1/P1
    mlp(D, H, S1, &S2,     rdP1, rdP2, rdP1, wrP1, sb, OW1H, OW1L, RS128, bias+256, OW2H, OW2L, bn, hk8, hk16, rn7, g7, lane);
    epi_slot(D, bias + 320, false, S1, wrP1, g7, lane);
    // i7 = AND(i5, i6) -> S0/P0
    mlp(D, H, S0, &S1,     rdP0, rdP1, rdP0, wrP0, sb, AW1H, AW1L, RS128, bias+128, AW2H, AW2L, bn, hk8, hk16, rn7, g7, lane);
    epi_slot(D, bias + 192, false, S0, wrP0, g7, lane);
    // n7 = NOT(i7) -> S1/P1
    mlp(D, H, S0, nullptr, rdP0, 0,    rdP1, wrP1, sb, NW1H, NW1L, RS64,  bias+0,   NW2H, NW2L, bn, hk8, hk16, rn7, g7, lane);
    epi_slot(D, bias + 64, false, S1, wrP1, g7, lane);
    gather(S2, wrP2, g7, item, seq[r1*5 + 4], seq[r2*5 + 4], lane);   // e4 -> S2/P2
    // i8 = OR(n7, e4) -> S0/P0
    mlp(D, H, S1, &S2,     rdP1, rdP2, rdP0, wrP0, sb, OW1H, OW1L, RS128, bias+256, OW2H, OW2L, bn, hk8, hk16, rn7, g7, lane);
    epi_slot(D, bias + 320, false, S0, wrP0, g7, lane);
    // enc_not = NOT(i8) -> S1/P1
    mlp(D, H, S0, nullptr, rdP0, 0,    rdP1, wrP1, sb, NW1H, NW1L, RS64,  bias+0,   NW2H, NW2L, bn, hk8, hk16, rn7, g7, lane);
    epi_slot(D, bias + 64, false, S1, wrP1, g7, lane);
    gather(S2, wrP2, g7, item, post[r1], post[r2], lane);             // pos_e -> S2/P2
    // encoded_pos = OR(enc_not, pos_e)   (H uses free buffer P0)
    mlp(D, H, S1, &S2,     rdP1, rdP2, rdP0, wrP0, sb, OW1H, OW1L, RS128, bias+256, OW2H, OW2L, bn, hk8, hk16, rn7, g7, lane);
    final_epi(D, bias + 320, tv, tnorm, out, r1, lane);
    gather(S2, wrP2, g7, item, negt[r1], negt[r2], lane);             // neg_e -> S2/P2
    // encoded_neg = OR(enc_not, neg_e)
    mlp(D, H, S1, &S2,     rdP1, rdP2, rdP0, wrP0, sb, OW1H, OW1L, RS128, bias+256, OW2H, OW2L, bn, hk8, hk16, rn7, g7, lane);
    final_epi(D, bias + 320, tv, tnorm, out + batch, r1, lane);
}

extern "C" void kernel_launch(void* const* d_in, const int* in_sizes, int n_in,
                              void* d_out, int out_size) {
    const int*   seq   = (const int*)  d_in[0];
    const int*   pos_t = (const int*)  d_in[1];
    const int*   neg_t = (const int*)  d_in[2];
    const float* item  = (const float*)d_in[3];
    const float* tvec  = (const float*)d_in[4];
    const float* nW1 = (const float*)d_in[5];
    const float* nb1 = (const float*)d_in[6];
    const float* nW2 = (const float*)d_in[7];
    const float* nb2 = (const float*)d_in[8];
    const float* aW1 = (const float*)d_in[9];
    const float* ab1 = (const float*)d_in[10];
    const float* aW2 = (const float*)d_in[11];
    const float* ab2 = (const float*)d_in[12];
    const float* oW1 = (const float*)d_in[13];
    const float* ob1 = (const float*)d_in[14];
    const float* oW2 = (const float*)d_in[15];
    const float* ob2 = (const float*)d_in[16];
    float* out = (float*)d_out;

    int batch = in_sizes[1];
    convert_weights<<<128, 256>>>(nW1, nW2, aW1, aW2, oW1, oW2);

    int grid = (batch + TILE - 1) / TILE;
    cudaFuncSetAttribute(logicnet_mma, cudaFuncAttributeMaxDynamicSharedMemorySize, SMEM_REQ);
    logicnet_mma<<<grid, NT, SMEM_REQ>>>(
        seq, pos_t, neg_t, item, tvec,
        nb1, nb2, ab1, ab2, ob1, ob2, out, batch);
}